// round 1
// baseline (speedup 1.0000x reference)
#include <cuda_runtime.h>
#include <math.h>

#define B_ 4
#define S_ 4096
#define D_ 1024
#define H_ 16
#define HD_ 64
#define M_ (B_*S_)          // 16384
#define BH_ (B_*H_)         // 64
#define SPLIT_ 16

// ---------------- scratch (device globals; no allocation) ----------------
__device__ __align__(16) float g_Q[(size_t)M_ * D_];   // [b,h,s,d]
__device__ __align__(16) float g_K[(size_t)M_ * D_];   // [b,h,s,d]
__device__ __align__(16) float g_V[(size_t)M_ * D_];   // [b,h,s,d]
__device__ __align__(16) float g_O[(size_t)M_ * D_];   // [b,s,h*hd+e] row-major
__device__ __align__(16) float g_KVpart[(size_t)BH_ * SPLIT_ * HD_ * HD_];
__device__ __align__(16) float g_KSpart[(size_t)BH_ * SPLIT_ * HD_];
__device__ __align__(16) float g_KV[(size_t)BH_ * HD_ * HD_];
__device__ __align__(16) float g_KS[(size_t)BH_ * HD_];

// ---------------------------------------------------------------------------
// GEMM  C = A @ W^T + bias, A:[M,1024] row-major, W:[1024,1024] row-major.
// Block tile 128(M) x 64(N), BK=8, 128 threads, 8x8 per-thread micro-tile.
// Thread columns are {c, c+32} pairs so RoPE's rotate_half stays in-thread.
// MODE: 0 = plain -> out (row-major [M,1024])
//       1 = rope+elu -> g_Q (bhsd)   2 = rope+elu -> g_K   3 = bias -> g_V
// ---------------------------------------------------------------------------
template<int MODE>
__global__ __launch_bounds__(128)
void gemm_nt(const float* __restrict__ A, const float* __restrict__ W,
             const float* __restrict__ bias, float* __restrict__ out,
             const float* __restrict__ cs, const float* __restrict__ sn)
{
    __shared__ __align__(16) float As[8][128];
    __shared__ __align__(16) float Bs[8][64];

    const int tid = threadIdx.x;
    const int ty  = tid >> 3;        // 0..15 -> row groups
    const int tx  = tid & 7;         // 0..7  -> col groups
    const int n0  = blockIdx.x * 64; // N tile (x-fast => W band L2-resident)
    const int m0  = blockIdx.y * 128;

    const float* Ap   = (MODE == 0) ? (const float*)g_O : A;
    const float* arow = Ap + (size_t)(m0 + tid) * D_;
    const float* wrow = W + (size_t)(n0 + (tid >> 1)) * D_;
    const int    wseg = (tid & 1) * 4;

    float acc[8][8];
#pragma unroll
    for (int i = 0; i < 8; i++)
#pragma unroll
        for (int j = 0; j < 8; j++) acc[i][j] = 0.f;

    for (int k0 = 0; k0 < D_; k0 += 8) {
        float4 a0 = *(const float4*)(arow + k0);
        float4 a1 = *(const float4*)(arow + k0 + 4);
        float4 bv = *(const float4*)(wrow + k0 + wseg);
        __syncthreads();
        As[0][tid] = a0.x; As[1][tid] = a0.y; As[2][tid] = a0.z; As[3][tid] = a0.w;
        As[4][tid] = a1.x; As[5][tid] = a1.y; As[6][tid] = a1.z; As[7][tid] = a1.w;
        {
            int r = tid >> 1;
            Bs[wseg + 0][r] = bv.x; Bs[wseg + 1][r] = bv.y;
            Bs[wseg + 2][r] = bv.z; Bs[wseg + 3][r] = bv.w;
        }
        __syncthreads();
#pragma unroll
        for (int k = 0; k < 8; k++) {
            float4 x0 = *(const float4*)&As[k][ty * 4];
            float4 x1 = *(const float4*)&As[k][64 + ty * 4];
            float4 y0 = *(const float4*)&Bs[k][tx * 4];
            float4 y1 = *(const float4*)&Bs[k][32 + tx * 4];
            float a[8] = {x0.x, x0.y, x0.z, x0.w, x1.x, x1.y, x1.z, x1.w};
            float b[8] = {y0.x, y0.y, y0.z, y0.w, y1.x, y1.y, y1.z, y1.w};
#pragma unroll
            for (int i = 0; i < 8; i++)
#pragma unroll
                for (int j = 0; j < 8; j++)
                    acc[i][j] = fmaf(a[i], b[j], acc[i][j]);
        }
    }

    // ---------------- epilogue ----------------
#pragma unroll
    for (int i = 0; i < 8; i++) {
        const int row = (i < 4) ? (ty * 4 + i) : (64 + ty * 4 + i - 4);
        const int m   = m0 + row;
        if (MODE == 0) {
#pragma unroll
            for (int j = 0; j < 8; j++) {
                int col = (j < 4) ? (tx * 4 + j) : (32 + tx * 4 + j - 4);
                out[(size_t)m * D_ + n0 + col] = acc[i][j] + bias[n0 + col];
            }
        } else {
            const int b = m >> 12;       // m / S_
            const int s = m & (S_ - 1);
            const int h = blockIdx.x;    // n0/64 == head index
            float* dst = (MODE == 1) ? g_Q : (MODE == 2) ? g_K : g_V;
            const size_t base = (((size_t)b * H_ + h) * S_ + s) * HD_;
            if (MODE == 3) {
#pragma unroll
                for (int j = 0; j < 8; j++) {
                    int col = (j < 4) ? (tx * 4 + j) : (32 + tx * 4 + j - 4);
                    dst[base + col] = acc[i][j] + bias[n0 + col];
                }
            } else {
#pragma unroll
                for (int j = 0; j < 4; j++) {
                    int c1 = tx * 4 + j;     // < 32
                    int c2 = c1 + 32;
                    float x1 = acc[i][j]     + bias[n0 + c1];
                    float x2 = acc[i][j + 4] + bias[n0 + c2];
                    float cv1 = cs[s * HD_ + c1], sv1 = sn[s * HD_ + c1];
                    float cv2 = cs[s * HD_ + c2], sv2 = sn[s * HD_ + c2];
                    // rope: d<32: q*c - q[d+32]*s ; d>=32: q*c + q[d-32]*s
                    float r1 = x1 * cv1 - x2 * sv1;
                    float r2 = x2 * cv2 + x1 * sv2;
                    // elu feature map: max(x>0 ? x+1 : exp(x), 0.01)
                    r1 = (r1 > 0.f) ? (r1 + 1.f) : expf(r1);
                    r2 = (r2 > 0.f) ? (r2 + 1.f) : expf(r2);
                    dst[base + c1] = fmaxf(r1, 0.01f);
                    dst[base + c2] = fmaxf(r2, 0.01f);
                }
            }
        }
    }
}

// ---------------------------------------------------------------------------
// KV[bh][d][e] = sum_s K[bh][s][d] * V[bh][s][e]; KS[bh][d] = sum_s K[bh][s][d]
// split-S = 16 partials (deterministic: no atomics), reduced by kv_reduce.
// Grid (SPLIT_, BH_), 64 threads, each thread an 8x8 (d,e) micro-tile.
// ---------------------------------------------------------------------------
__global__ __launch_bounds__(64)
void kv_kernel()
{
    __shared__ __align__(16) float Ks[16 * 64];
    __shared__ __align__(16) float Vs[16 * 64];
    const int t  = threadIdx.x;
    const int bh = blockIdx.y;
    const int sp = blockIdx.x;
    const int d0 = (t & 7) * 8;
    const int e0 = (t >> 3) * 8;
    const int schunk = S_ / SPLIT_;  // 256
    const size_t base = ((size_t)bh * S_ + (size_t)sp * schunk) * HD_;

    float acc[8][8];
    float ks[8];
#pragma unroll
    for (int i = 0; i < 8; i++) {
        ks[i] = 0.f;
#pragma unroll
        for (int j = 0; j < 8; j++) acc[i][j] = 0.f;
    }

    for (int sc = 0; sc < schunk; sc += 16) {
        const float4* srk = (const float4*)(g_K + base + (size_t)sc * HD_);
        const float4* srv = (const float4*)(g_V + base + (size_t)sc * HD_);
        __syncthreads();
#pragma unroll
        for (int i = 0; i < 4; i++) {       // 16x64 tile is contiguous: flat copy
            ((float4*)Ks)[t + i * 64] = srk[t + i * 64];
            ((float4*)Vs)[t + i * 64] = srv[t + i * 64];
        }
        __syncthreads();
#pragma unroll
        for (int k = 0; k < 16; k++) {
            float4 ka = *(const float4*)&Ks[k * 64 + d0];
            float4 kb = *(const float4*)&Ks[k * 64 + d0 + 4];
            float4 va = *(const float4*)&Vs[k * 64 + e0];
            float4 vb = *(const float4*)&Vs[k * 64 + e0 + 4];
            float a[8] = {ka.x, ka.y, ka.z, ka.w, kb.x, kb.y, kb.z, kb.w};
            float v[8] = {va.x, va.y, va.z, va.w, vb.x, vb.y, vb.z, vb.w};
#pragma unroll
            for (int i = 0; i < 8; i++)
#pragma unroll
                for (int j = 0; j < 8; j++)
                    acc[i][j] = fmaf(a[i], v[j], acc[i][j]);
            if (e0 == 0) {
#pragma unroll
                for (int i = 0; i < 8; i++) ks[i] += a[i];
            }
        }
    }
    const size_t pb = ((size_t)bh * SPLIT_ + sp) * (HD_ * HD_);
#pragma unroll
    for (int i = 0; i < 8; i++) {
        *(float4*)&g_KVpart[pb + (d0 + i) * HD_ + e0] =
            make_float4(acc[i][0], acc[i][1], acc[i][2], acc[i][3]);
        *(float4*)&g_KVpart[pb + (d0 + i) * HD_ + e0 + 4] =
            make_float4(acc[i][4], acc[i][5], acc[i][6], acc[i][7]);
    }
    if (e0 == 0) {
        const size_t kb2 = ((size_t)bh * SPLIT_ + sp) * HD_;
#pragma unroll
        for (int i = 0; i < 8; i++) g_KSpart[kb2 + d0 + i] = ks[i];
    }
}

__global__ void kv_reduce()
{
    const int N1 = BH_ * HD_ * HD_;  // 262144
    int g = blockIdx.x * blockDim.x + threadIdx.x;
    if (g < N1) {
        int bh  = g >> 12;
        int idx = g & (HD_ * HD_ - 1);
        float s = 0.f;
#pragma unroll
        for (int p = 0; p < SPLIT_; p++)
            s += g_KVpart[((size_t)bh * SPLIT_ + p) * (HD_ * HD_) + idx];
        g_KV[g] = s;
    } else if (g < N1 + BH_ * HD_) {
        int g2 = g - N1;
        int bh = g2 >> 6;
        int d  = g2 & 63;
        float s = 0.f;
#pragma unroll
        for (int p = 0; p < SPLIT_; p++)
            s += g_KSpart[((size_t)bh * SPLIT_ + p) * HD_ + d];
        g_KS[g2] = s;
    }
}

// ---------------------------------------------------------------------------
// out[bh][s][e] = (sum_d Q[bh][s][d] * KV[bh][d][e]) / (max(Q.KS,1)+1e-6)
// Writes g_O in [b, s, h*64+e] layout so the output projection is plain GEMM.
// Grid (S_/64, BH_), 128 threads; thread = 4 rows x 8 cols.
// ---------------------------------------------------------------------------
__global__ __launch_bounds__(128)
void apply_kernel()
{
    __shared__ __align__(16) float Qs[64][72];     // [d][row], padded stride
    __shared__ __align__(16) float KVs[64 * 64];
    __shared__ float KSs[64];

    const int t  = threadIdx.x;
    const int bh = blockIdx.y;
    const int b  = bh >> 4;
    const int h  = bh & 15;
    const int s0 = blockIdx.x * 64;

    {   // KV (4096 floats) + KS
        const float4* src = (const float4*)(g_KV + (size_t)bh * (HD_ * HD_));
#pragma unroll
        for (int i = 0; i < 8; i++)
            ((float4*)KVs)[t + i * 128] = src[t + i * 128];
        if (t < 64) KSs[t] = g_KS[bh * HD_ + t];
    }
    {   // Q tile (64 rows x 64), transposed into [d][row]
        const float4* src = (const float4*)(g_Q + ((size_t)bh * S_ + s0) * HD_);
#pragma unroll
        for (int i = 0; i < 8; i++) {
            int p = t + i * 128;
            float4 v = src[p];
            int row = p >> 4;
            int d   = (p & 15) * 4;
            Qs[d][row] = v.x; Qs[d + 1][row] = v.y;
            Qs[d + 2][row] = v.z; Qs[d + 3][row] = v.w;
        }
    }
    __syncthreads();

    const int ty = t >> 3;      // 0..15 -> rows ty*4..+3
    const int tx = t & 7;       // 0..7  -> cols tx*8..+7
    const int e0 = tx * 8;
    float acc[4][8];
    float an[4];
#pragma unroll
    for (int i = 0; i < 4; i++) {
        an[i] = 0.f;
#pragma unroll
        for (int j = 0; j < 8; j++) acc[i][j] = 0.f;
    }

#pragma unroll 8
    for (int d = 0; d < 64; d++) {
        float4 q  = *(const float4*)&Qs[d][ty * 4];
        float4 k0 = *(const float4*)&KVs[d * 64 + e0];
        float4 k1 = *(const float4*)&KVs[d * 64 + e0 + 4];
        float ksd = KSs[d];
        float a[4] = {q.x, q.y, q.z, q.w};
        float v[8] = {k0.x, k0.y, k0.z, k0.w, k1.x, k1.y, k1.z, k1.w};
#pragma unroll
        for (int i = 0; i < 4; i++) {
#pragma unroll
            for (int j = 0; j < 8; j++)
                acc[i][j] = fmaf(a[i], v[j], acc[i][j]);
            an[i] = fmaf(a[i], ksd, an[i]);
        }
    }

#pragma unroll
    for (int i = 0; i < 4; i++) {
        int s = s0 + ty * 4 + i;
        float nrm = fmaxf(an[i], 1.0f) + 1e-6f;
        float inv = 1.0f / nrm;
        float* dst = &g_O[((size_t)b * S_ + s) * D_ + h * HD_ + e0];
        *(float4*)dst =
            make_float4(acc[i][0] * inv, acc[i][1] * inv, acc[i][2] * inv, acc[i][3] * inv);
        *(float4*)(dst + 4) =
            make_float4(acc[i][4] * inv, acc[i][5] * inv, acc[i][6] * inv, acc[i][7] * inv);
    }
}

// ---------------------------------------------------------------------------
extern "C" void kernel_launch(void* const* d_in, const int* in_sizes, int n_in,
                              void* d_out, int out_size)
{
    (void)in_sizes; (void)n_in; (void)out_size;
    const float* query = (const float*)d_in[0];
    const float* key   = (const float*)d_in[1];
    const float* value = (const float*)d_in[2];
    const float* cosp  = (const float*)d_in[3];
    const float* sinp  = (const float*)d_in[4];
    const float* Wq = (const float*)d_in[5];
    const float* bq = (const float*)d_in[6];
    const float* Wk = (const float*)d_in[7];
    const float* bk = (const float*)d_in[8];
    const float* Wv = (const float*)d_in[9];
    const float* bv = (const float*)d_in[10];
    const float* Wo = (const float*)d_in[11];
    const float* bo = (const float*)d_in[12];
    float* out = (float*)d_out;

    dim3 gg(D_ / 64, M_ / 128);   // (16, 128): x-fast keeps W band in L2

    gemm_nt<1><<<gg, 128>>>(query, Wq, bq, nullptr, cosp, sinp);
    gemm_nt<2><<<gg, 128>>>(key,   Wk, bk, nullptr, cosp, sinp);
    gemm_nt<3><<<gg, 128>>>(value, Wv, bv, nullptr, cosp, sinp);

    kv_kernel<<<dim3(SPLIT_, BH_), 64>>>();
    kv_reduce<<<(BH_ * HD_ * HD_ + BH_ * HD_ + 255) / 256, 256>>>();
    apply_kernel<<<dim3(S_ / 64, BH_), 128>>>();

    gemm_nt<0><<<gg, 128>>>(nullptr, Wo, bo, out, nullptr, nullptr);
}

// round 4
// speedup vs baseline: 2.6319x; 2.6319x over previous
#include <cuda_runtime.h>
#include <cstdint>
#include <math.h>

#define B_ 4
#define S_ 4096
#define D_ 1024
#define H_ 16
#define HD_ 64
#define M_ (B_*S_)          // 16384
#define BH_ (B_*H_)         // 64
#define SPLIT_ 16

// GEMM tiling (mma.sync tf32 path — compute_100-portable)
#define TM 128
#define TN 128
#define BK 32
#define NCH (D_/BK)                 // 32 chunks
#define PITCH 36                    // floats per smem row (conflict-free)
#define STG_FLOATS (128*PITCH)      // per-stage A or B floats = 4608
#define SMEM_BYTES (6*STG_FLOATS*4) // 3 stages x (A+B) = 110592 B

// ---------------- scratch (device globals; no allocation) ----------------
__device__ __align__(16) float g_Q[(size_t)M_ * D_];   // [b,h,s,d]
__device__ __align__(16) float g_K[(size_t)M_ * D_];
__device__ __align__(16) float g_V[(size_t)M_ * D_];
__device__ __align__(16) float g_O[(size_t)M_ * D_];   // [b,s,h*64+e], tf32-rounded
__device__ __align__(16) float g_Ar[(size_t)M_ * D_];  // tf32-rounded activations
__device__ __align__(16) float g_Wr[(size_t)D_ * D_];  // tf32-rounded weights
__device__ __align__(16) float g_KVpart[(size_t)BH_ * SPLIT_ * HD_ * HD_];
__device__ __align__(16) float g_KSpart[(size_t)BH_ * SPLIT_ * HD_];
__device__ __align__(16) float g_KV[(size_t)BH_ * HD_ * HD_];
__device__ __align__(16) float g_KS[(size_t)BH_ * HD_];

// ---------------- helpers ----------------
__device__ __forceinline__ uint32_t smem_u32(const void* p) {
    uint32_t a;
    asm("{ .reg .u64 t; cvta.to.shared.u64 t, %1; cvt.u32.u64 %0, t; }" : "=r"(a) : "l"(p));
    return a;
}
#define CP16(dst, src) asm volatile("cp.async.cg.shared.global [%0], [%1], 16;" :: "r"(dst), "l"(src))
#define CP_COMMIT()    asm volatile("cp.async.commit_group;" ::: "memory")
#define CP_WAIT1()     asm volatile("cp.async.wait_group 1;" ::: "memory")

#define MMA_TF32(c, a, b) \
    asm volatile("mma.sync.aligned.m16n8k8.row.col.f32.tf32.tf32.f32 " \
        "{%0,%1,%2,%3}, {%4,%5,%6,%7}, {%8,%9}, {%0,%1,%2,%3};" \
        : "+f"((c)[0]), "+f"((c)[1]), "+f"((c)[2]), "+f"((c)[3]) \
        : "r"((a)[0]), "r"((a)[1]), "r"((a)[2]), "r"((a)[3]), \
          "r"((b)[0]), "r"((b)[1]))

__device__ __forceinline__ float rtf32(float x) {
    uint32_t u = __float_as_uint(x);
    u = (u + 0xFFFu + ((u >> 13) & 1u)) & 0xFFFFE000u;   // round-to-nearest-even tf32
    return __uint_as_float(u);
}

// ---------------------------------------------------------------------------
// elementwise round-to-nearest tf32 (removes MMA truncation bias)
// ---------------------------------------------------------------------------
__global__ void round_tf32_kernel(const float4* __restrict__ src, float4* __restrict__ dst, int n4)
{
    int i = blockIdx.x * blockDim.x + threadIdx.x;
    if (i < n4) {
        float4 v = src[i];
        v.x = rtf32(v.x); v.y = rtf32(v.y); v.z = rtf32(v.z); v.w = rtf32(v.w);
        dst[i] = v;
    }
}

// ---------------------------------------------------------------------------
// tf32 mma.sync GEMM  C = A @ W^T + bias  (A:[16384,1024], W:[1024,1024])
// 128x128 tile, BK=32, 3-stage cp.async, warp tile 64x32 (n-tiles at
// {0,32,64,96} so RoPE pairs (j, j+32) stay in one thread).
// MODE: 0 plain -> out ; 1 rope+elu -> g_Q ; 2 rope+elu -> g_K ; 3 bias -> g_V
// ---------------------------------------------------------------------------
template<int MODE>
__global__ __launch_bounds__(256, 1)
void gemm_tc(const float* __restrict__ A, const float* __restrict__ W,
             const float* __restrict__ bias, float* __restrict__ out,
             const float* __restrict__ cs, const float* __restrict__ sn)
{
    extern __shared__ __align__(16) float sm[];
    float* smA = sm;                     // 3 stages x 128 x PITCH
    float* smB = sm + 3 * STG_FLOATS;

    const int tid = threadIdx.x;
    const int n0  = blockIdx.x * TN;
    const int m0  = blockIdx.y * TM;
    const float* __restrict__ Ap = (MODE == 0) ? (const float*)g_O : A;

    const int lane   = tid & 31;
    const int wid    = tid >> 5;
    const int wm64   = (wid & 1) * 64;
    const int wn8    = (wid >> 1) * 8;
    const int qrow   = lane >> 2;
    const int qcol   = lane & 3;

    const uint32_t smA_u = smem_u32(smA);
    const uint32_t smB_u = smem_u32(smB);

    auto load_chunk = [&](int ch, int st) {
        const int k0 = ch * BK;
        const uint32_t aB = smA_u + (uint32_t)st * STG_FLOATS * 4;
        const uint32_t bB = smB_u + (uint32_t)st * STG_FLOATS * 4;
#pragma unroll
        for (int j = 0; j < 4; j++) {                 // A: 128 rows x 8 x 16B
            int q = tid + j * 256, row = q >> 3, seg = q & 7;
            CP16(aB + (uint32_t)(row * PITCH + seg * 4) * 4,
                 Ap + (size_t)(m0 + row) * D_ + k0 + seg * 4);
        }
#pragma unroll
        for (int j = 0; j < 4; j++) {                 // B(W): 128 rows x 8 x 16B
            int q = tid + j * 256, row = q >> 3, seg = q & 7;
            CP16(bB + (uint32_t)(row * PITCH + seg * 4) * 4,
                 W + (size_t)(n0 + row) * D_ + k0 + seg * 4);
        }
    };

    float acc[4][4][4];
#pragma unroll
    for (int mt = 0; mt < 4; mt++)
#pragma unroll
        for (int nt = 0; nt < 4; nt++)
#pragma unroll
            for (int r = 0; r < 4; r++) acc[mt][nt][r] = 0.f;

    load_chunk(0, 0); CP_COMMIT();
    load_chunk(1, 1); CP_COMMIT();

    for (int i = 0; i < NCH; i++) {
        CP_WAIT1();
        __syncthreads();
        if (i + 2 < NCH) load_chunk(i + 2, (i + 2) % 3);
        CP_COMMIT();

        const int st = i % 3;
        const float* As = smA + st * STG_FLOATS;
        const float* Bs = smB + st * STG_FLOATS;
#pragma unroll
        for (int kk = 0; kk < 4; kk++) {
            uint32_t bf[4][2];
#pragma unroll
            for (int nt = 0; nt < 4; nt++) {
                const float* bp = Bs + (wn8 + nt * 32 + qrow) * PITCH + kk * 8 + qcol;
                bf[nt][0] = __float_as_uint(bp[0]);
                bf[nt][1] = __float_as_uint(bp[4]);
            }
#pragma unroll
            for (int mt = 0; mt < 4; mt++) {
                const float* ap = As + (wm64 + mt * 16 + qrow) * PITCH + kk * 8 + qcol;
                uint32_t af[4];
                af[0] = __float_as_uint(ap[0]);
                af[1] = __float_as_uint(ap[8 * PITCH]);
                af[2] = __float_as_uint(ap[4]);
                af[3] = __float_as_uint(ap[8 * PITCH + 4]);
#pragma unroll
                for (int nt = 0; nt < 4; nt++) MMA_TF32(acc[mt][nt], af, bf[nt]);
            }
        }
    }

    // ---------------- epilogue ----------------
#pragma unroll
    for (int mt = 0; mt < 4; mt++) {
#pragma unroll
        for (int r = 0; r < 4; r++) {
            const int row = wm64 + mt * 16 + qrow + (r >> 1) * 8;
            const int m = m0 + row;
            const int b = m >> 12;
            const int s = m & (S_ - 1);
            const int cc = 2 * qcol + (r & 1);

            if (MODE == 0) {
#pragma unroll
                for (int nt = 0; nt < 4; nt++) {
                    int col = wn8 + nt * 32 + cc;
                    out[(size_t)m * D_ + n0 + col] = acc[mt][nt][r] + bias[n0 + col];
                }
            } else if (MODE == 3) {
#pragma unroll
                for (int nt = 0; nt < 4; nt++) {
                    int col = wn8 + nt * 32 + cc;
                    int h = (n0 + col) >> 6, e = col & 63;
                    g_V[(((size_t)b * H_ + h) * S_ + s) * HD_ + e] =
                        acc[mt][nt][r] + bias[n0 + col];
                }
            } else {
                float* dstb = (MODE == 1) ? g_Q : g_K;
#pragma unroll
                for (int half = 0; half < 2; half++) {
                    const int p = half * 2;
                    const int h = (n0 >> 6) + half;
                    const int j = wn8 + cc;                      // 0..31
                    float x1 = acc[mt][p][r]     + bias[h * HD_ + j];
                    float x2 = acc[mt][p + 1][r] + bias[h * HD_ + j + 32];
                    float c1 = cs[s * HD_ + j],      s1 = sn[s * HD_ + j];
                    float c2 = cs[s * HD_ + j + 32], s2 = sn[s * HD_ + j + 32];
                    float r1 = x1 * c1 - x2 * s1;
                    float r2 = x2 * c2 + x1 * s2;
                    r1 = (r1 > 0.f) ? (r1 + 1.f) : expf(r1);
                    r2 = (r2 > 0.f) ? (r2 + 1.f) : expf(r2);
                    float* d = dstb + (((size_t)b * H_ + h) * S_ + s) * HD_;
                    d[j]      = fmaxf(r1, 0.01f);
                    d[j + 32] = fmaxf(r2, 0.01f);
                }
            }
        }
    }
}

// ---------------------------------------------------------------------------
// KV[bh][d][e] = sum_s K[bh][s][d] * V[bh][s][e]; KS[bh][d] = sum_s K
// ---------------------------------------------------------------------------
__global__ __launch_bounds__(128)
void kv_kernel()
{
    __shared__ __align__(16) float Ks[16 * 64];
    __shared__ __align__(16) float Vs[16 * 64];
    const int t  = threadIdx.x;
    const int bh = blockIdx.y;
    const int sp = blockIdx.x;
    const int d0 = (t >> 4) * 8;
    const int e0 = (t & 15) * 4;
    const int schunk = S_ / SPLIT_;
    const size_t base = ((size_t)bh * S_ + (size_t)sp * schunk) * HD_;

    float acc[8][4];
    float ks[8];
#pragma unroll
    for (int i = 0; i < 8; i++) {
        ks[i] = 0.f;
#pragma unroll
        for (int j = 0; j < 4; j++) acc[i][j] = 0.f;
    }

    for (int sc = 0; sc < schunk; sc += 16) {
        const float4* srk = (const float4*)(g_K + base + (size_t)sc * HD_);
        const float4* srv = (const float4*)(g_V + base + (size_t)sc * HD_);
        __syncthreads();
#pragma unroll
        for (int i = 0; i < 2; i++) {
            ((float4*)Ks)[t + i * 128] = srk[t + i * 128];
            ((float4*)Vs)[t + i * 128] = srv[t + i * 128];
        }
        __syncthreads();
#pragma unroll
        for (int k = 0; k < 16; k++) {
            float4 ka = *(const float4*)&Ks[k * 64 + d0];
            float4 kb = *(const float4*)&Ks[k * 64 + d0 + 4];
            float4 va = *(const float4*)&Vs[k * 64 + e0];
            float a[8] = {ka.x, ka.y, ka.z, ka.w, kb.x, kb.y, kb.z, kb.w};
            float v[4] = {va.x, va.y, va.z, va.w};
#pragma unroll
            for (int i = 0; i < 8; i++)
#pragma unroll
                for (int j = 0; j < 4; j++)
                    acc[i][j] = fmaf(a[i], v[j], acc[i][j]);
            if (e0 == 0) {
#pragma unroll
                for (int i = 0; i < 8; i++) ks[i] += a[i];
            }
        }
    }
    const size_t pb = ((size_t)bh * SPLIT_ + sp) * (HD_ * HD_);
#pragma unroll
    for (int i = 0; i < 8; i++)
        *(float4*)&g_KVpart[pb + (d0 + i) * HD_ + e0] =
            make_float4(acc[i][0], acc[i][1], acc[i][2], acc[i][3]);
    if (e0 == 0) {
        const size_t kb2 = ((size_t)bh * SPLIT_ + sp) * HD_;
#pragma unroll
        for (int i = 0; i < 8; i++) g_KSpart[kb2 + d0 + i] = ks[i];
    }
}

__global__ void kv_reduce()
{
    const int N1 = BH_ * HD_ * HD_;
    int g = blockIdx.x * blockDim.x + threadIdx.x;
    if (g < N1) {
        int bh  = g >> 12;
        int idx = g & (HD_ * HD_ - 1);
        float s = 0.f;
#pragma unroll
        for (int p = 0; p < SPLIT_; p++)
            s += g_KVpart[((size_t)bh * SPLIT_ + p) * (HD_ * HD_) + idx];
        g_KV[g] = s;
    } else if (g < N1 + BH_ * HD_) {
        int g2 = g - N1;
        int bh = g2 >> 6, d = g2 & 63;
        float s = 0.f;
#pragma unroll
        for (int p = 0; p < SPLIT_; p++)
            s += g_KSpart[((size_t)bh * SPLIT_ + p) * HD_ + d];
        g_KS[g2] = s;
    }
}

// ---------------------------------------------------------------------------
// out = (Q . KV) / clip(Q . KSum); writes g_O rounded to tf32 for out-proj
// ---------------------------------------------------------------------------
__global__ __launch_bounds__(128)
void apply_kernel()
{
    __shared__ __align__(16) float Qs[64][72];
    __shared__ __align__(16) float KVs[64 * 64];
    __shared__ float KSs[64];

    const int t  = threadIdx.x;
    const int bh = blockIdx.y;
    const int b  = bh >> 4;
    const int h  = bh & 15;
    const int s0 = blockIdx.x * 64;

    {
        const float4* src = (const float4*)(g_KV + (size_t)bh * (HD_ * HD_));
#pragma unroll
        for (int i = 0; i < 8; i++)
            ((float4*)KVs)[t + i * 128] = src[t + i * 128];
        if (t < 64) KSs[t] = g_KS[bh * HD_ + t];
    }
    {
        const float4* src = (const float4*)(g_Q + ((size_t)bh * S_ + s0) * HD_);
#pragma unroll
        for (int i = 0; i < 8; i++) {
            int p = t + i * 128;
            float4 v = src[p];
            int row = p >> 4, d = (p & 15) * 4;
            Qs[d][row] = v.x; Qs[d + 1][row] = v.y;
            Qs[d + 2][row] = v.z; Qs[d + 3][row] = v.w;
        }
    }
    __syncthreads();

    const int ty = t >> 3, tx = t & 7;
    const int e0 = tx * 8;
    float acc[4][8], an[4];
#pragma unroll
    for (int i = 0; i < 4; i++) {
        an[i] = 0.f;
#pragma unroll
        for (int j = 0; j < 8; j++) acc[i][j] = 0.f;
    }

#pragma unroll 8
    for (int d = 0; d < 64; d++) {
        float4 q  = *(const float4*)&Qs[d][ty * 4];
        float4 k0 = *(const float4*)&KVs[d * 64 + e0];
        float4 k1 = *(const float4*)&KVs[d * 64 + e0 + 4];
        float ksd = KSs[d];
        float a[4] = {q.x, q.y, q.z, q.w};
        float v[8] = {k0.x, k0.y, k0.z, k0.w, k1.x, k1.y, k1.z, k1.w};
#pragma unroll
        for (int i = 0; i < 4; i++) {
#pragma unroll
            for (int j = 0; j < 8; j++)
                acc[i][j] = fmaf(a[i], v[j], acc[i][j]);
            an[i] = fmaf(a[i], ksd, an[i]);
        }
    }

#pragma unroll
    for (int i = 0; i < 4; i++) {
        int s = s0 + ty * 4 + i;
        float inv = 1.0f / (fmaxf(an[i], 1.0f) + 1e-6f);
        float* dst = &g_O[((size_t)b * S_ + s) * D_ + h * HD_ + e0];
        *(float4*)dst = make_float4(rtf32(acc[i][0] * inv), rtf32(acc[i][1] * inv),
                                    rtf32(acc[i][2] * inv), rtf32(acc[i][3] * inv));
        *(float4*)(dst + 4) = make_float4(rtf32(acc[i][4] * inv), rtf32(acc[i][5] * inv),
                                          rtf32(acc[i][6] * inv), rtf32(acc[i][7] * inv));
    }
}

// ---------------------------------------------------------------------------
extern "C" void kernel_launch(void* const* d_in, const int* in_sizes, int n_in,
                              void* d_out, int out_size)
{
    (void)in_sizes; (void)n_in; (void)out_size;
    const float* query = (const float*)d_in[0];
    const float* key   = (const float*)d_in[1];
    const float* value = (const float*)d_in[2];
    const float* cosp  = (const float*)d_in[3];
    const float* sinp  = (const float*)d_in[4];
    const float* Wq = (const float*)d_in[5];
    const float* bq = (const float*)d_in[6];
    const float* Wk = (const float*)d_in[7];
    const float* bk = (const float*)d_in[8];
    const float* Wv = (const float*)d_in[9];
    const float* bv = (const float*)d_in[10];
    const float* Wo = (const float*)d_in[11];
    const float* bo = (const float*)d_in[12];
    float* out = (float*)d_out;

    float* pAr = nullptr; float* pWr = nullptr;
    cudaGetSymbolAddress((void**)&pAr, g_Ar);
    cudaGetSymbolAddress((void**)&pWr, g_Wr);

    cudaFuncSetAttribute(gemm_tc<0>, cudaFuncAttributeMaxDynamicSharedMemorySize, SMEM_BYTES);
    cudaFuncSetAttribute(gemm_tc<1>, cudaFuncAttributeMaxDynamicSharedMemorySize, SMEM_BYTES);
    cudaFuncSetAttribute(gemm_tc<2>, cudaFuncAttributeMaxDynamicSharedMemorySize, SMEM_BYTES);
    cudaFuncSetAttribute(gemm_tc<3>, cudaFuncAttributeMaxDynamicSharedMemorySize, SMEM_BYTES);

    const int nA4 = M_ * D_ / 4;
    const int nW4 = D_ * D_ / 4;
    dim3 gt(D_ / TN, M_ / TM);        // (8, 128)

    round_tf32_kernel<<<(nA4 + 255) / 256, 256>>>((const float4*)query, (float4*)pAr, nA4);
    round_tf32_kernel<<<(nW4 + 255) / 256, 256>>>((const float4*)Wq, (float4*)pWr, nW4);
    gemm_tc<1><<<gt, 256, SMEM_BYTES>>>(pAr, pWr, bq, nullptr, cosp, sinp);

    round_tf32_kernel<<<(nA4 + 255) / 256, 256>>>((const float4*)key, (float4*)pAr, nA4);
    round_tf32_kernel<<<(nW4 + 255) / 256, 256>>>((const float4*)Wk, (float4*)pWr, nW4);
    gemm_tc<2><<<gt, 256, SMEM_BYTES>>>(pAr, pWr, bk, nullptr, cosp, sinp);

    round_tf32_kernel<<<(nA4 + 255) / 256, 256>>>((const float4*)value, (float4*)pAr, nA4);
    round_tf32_kernel<<<(nW4 + 255) / 256, 256>>>((const float4*)Wv, (float4*)pWr, nW4);
    gemm_tc<3><<<gt, 256, SMEM_BYTES>>>(pAr, pWr, bv, nullptr, cosp, sinp);

    kv_kernel<<<dim3(SPLIT_, BH_), 128>>>();
    kv_reduce<<<(BH_ * HD_ * HD_ + BH_ * HD_ + 255) / 256, 256>>>();
    apply_kernel<<<dim3(S_ / 64, BH_), 128>>>();

    round_tf32_kernel<<<(nW4 + 255) / 256, 256>>>((const float4*)Wo, (float4*)pWr, nW4);
    gemm_tc<0><<<gt, 256, SMEM_BYTES>>>(nullptr, pWr, bo, out, nullptr, nullptr);
}

// round 5
// speedup vs baseline: 2.8483x; 1.0822x over previous
#include <cuda_runtime.h>
#include <cstdint>
#include <math.h>

#define B_ 4
#define S_ 4096
#define D_ 1024
#define H_ 16
#define HD_ 64
#define M_ (B_*S_)          // 16384
#define BH_ (B_*H_)         // 64
#define SPLIT_ 16

// GEMM tiling (mma.sync tf32 path — compute_100-portable)
#define TM 128
#define TN 128
#define BK 32
#define NCH (D_/BK)                 // 32 chunks
#define PITCH 40                    // floats per smem row (conflict-free for LDS.64 + STS.128)
#define STG_FLOATS (128*PITCH)      // per-stage A or B floats = 5120
#define SMEM_BYTES (6*STG_FLOATS*4) // 3 stages x (A+B) = 122880 B

// ---------------- scratch (device globals; no allocation) ----------------
// NOTE: g_Ar / g_Wr / g_O hold K-PERMUTED data: within each 8-group of the
// contraction dim, new[2j] = old[j], new[2j+1] = old[j+4]. A and W share the
// permutation so the GEMM result is unchanged; it makes every mma fragment's
// two k-elements adjacent in smem (LDS.64 instead of 2x LDS.32).
__device__ __align__(16) float g_Q[(size_t)M_ * D_];   // [b,h,s,d] (unpermuted)
__device__ __align__(16) float g_K[(size_t)M_ * D_];
__device__ __align__(16) float g_V[(size_t)M_ * D_];
__device__ __align__(16) float g_O[(size_t)M_ * D_];   // [b,s,h*64+e], tf32+perm
__device__ __align__(16) float g_Ar[(size_t)M_ * D_];  // tf32+perm activations
__device__ __align__(16) float g_Wr[(size_t)D_ * D_];  // tf32+perm weights
__device__ __align__(16) float g_KVpart[(size_t)BH_ * SPLIT_ * HD_ * HD_];
__device__ __align__(16) float g_KSpart[(size_t)BH_ * SPLIT_ * HD_];
__device__ __align__(16) float g_KV[(size_t)BH_ * HD_ * HD_];
__device__ __align__(16) float g_KS[(size_t)BH_ * HD_];

// ---------------- helpers ----------------
__device__ __forceinline__ uint32_t smem_u32(const void* p) {
    uint32_t a;
    asm("{ .reg .u64 t; cvta.to.shared.u64 t, %1; cvt.u32.u64 %0, t; }" : "=r"(a) : "l"(p));
    return a;
}
#define CP16(dst, src) asm volatile("cp.async.cg.shared.global [%0], [%1], 16;" :: "r"(dst), "l"(src))
#define CP_COMMIT()    asm volatile("cp.async.commit_group;" ::: "memory")
#define CP_WAIT1()     asm volatile("cp.async.wait_group 1;" ::: "memory")

#define MMA_TF32(c, a, b) \
    asm volatile("mma.sync.aligned.m16n8k8.row.col.f32.tf32.tf32.f32 " \
        "{%0,%1,%2,%3}, {%4,%5,%6,%7}, {%8,%9}, {%0,%1,%2,%3};" \
        : "+f"((c)[0]), "+f"((c)[1]), "+f"((c)[2]), "+f"((c)[3]) \
        : "r"((a)[0]), "r"((a)[1]), "r"((a)[2]), "r"((a)[3]), \
          "r"((b)[0]), "r"((b)[1]))

__device__ __forceinline__ float rtf32(float x) {
    uint32_t u = __float_as_uint(x);
    u = (u + 0xFFFu + ((u >> 13) & 1u)) & 0xFFFFE000u;   // round-to-nearest-even tf32
    return __uint_as_float(u);
}

// ---------------------------------------------------------------------------
// fused tf32-round + k-permute: per 8-group, out = {o0,o4,o1,o5,o2,o6,o3,o7}
// ---------------------------------------------------------------------------
__global__ void round_perm_kernel(const float4* __restrict__ src, float4* __restrict__ dst, int n8)
{
    int i = blockIdx.x * blockDim.x + threadIdx.x;
    if (i < n8) {
        float4 v0 = src[2 * i];
        float4 v1 = src[2 * i + 1];
        dst[2 * i]     = make_float4(rtf32(v0.x), rtf32(v1.x), rtf32(v0.y), rtf32(v1.y));
        dst[2 * i + 1] = make_float4(rtf32(v0.z), rtf32(v1.z), rtf32(v0.w), rtf32(v1.w));
    }
}

// ---------------------------------------------------------------------------
// tf32 mma.sync GEMM  C = A @ W^T + bias  (A:[16384,1024], W:[1024,1024])
// 128x128 tile, BK=32, 3-stage cp.async, warp tile 64x32 (n-tiles at
// {0,32,64,96} so RoPE pairs (j, j+32) stay in one thread).
// Inputs are k-permuted; fragment gathers are LDS.64 and conflict-free.
// MODE: 0 plain -> out ; 1 rope+elu -> g_Q ; 2 rope+elu -> g_K ; 3 bias -> g_V
// ---------------------------------------------------------------------------
template<int MODE>
__global__ __launch_bounds__(256, 1)
void gemm_tc(const float* __restrict__ A, const float* __restrict__ W,
             const float* __restrict__ bias, float* __restrict__ out,
             const float* __restrict__ cs, const float* __restrict__ sn)
{
    extern __shared__ __align__(16) float sm[];
    float* smA = sm;                     // 3 stages x 128 x PITCH
    float* smB = sm + 3 * STG_FLOATS;

    const int tid = threadIdx.x;
    const int n0  = blockIdx.x * TN;
    const int m0  = blockIdx.y * TM;
    const float* __restrict__ Ap = (MODE == 0) ? (const float*)g_O : A;

    const int lane   = tid & 31;
    const int wid    = tid >> 5;
    const int wm64   = (wid & 1) * 64;
    const int wn8    = (wid >> 1) * 8;
    const int qrow   = lane >> 2;
    const int qcol   = lane & 3;

    const uint32_t smA_u = smem_u32(smA);
    const uint32_t smB_u = smem_u32(smB);

    auto load_chunk = [&](int ch, int st) {
        const int k0 = ch * BK;
        const uint32_t aB = smA_u + (uint32_t)st * STG_FLOATS * 4;
        const uint32_t bB = smB_u + (uint32_t)st * STG_FLOATS * 4;
#pragma unroll
        for (int j = 0; j < 4; j++) {                 // A: 128 rows x 8 x 16B
            int q = tid + j * 256, row = q >> 3, seg = q & 7;
            CP16(aB + (uint32_t)(row * PITCH + seg * 4) * 4,
                 Ap + (size_t)(m0 + row) * D_ + k0 + seg * 4);
        }
#pragma unroll
        for (int j = 0; j < 4; j++) {                 // B(W): 128 rows x 8 x 16B
            int q = tid + j * 256, row = q >> 3, seg = q & 7;
            CP16(bB + (uint32_t)(row * PITCH + seg * 4) * 4,
                 W + (size_t)(n0 + row) * D_ + k0 + seg * 4);
        }
    };

    float acc[4][4][4];
#pragma unroll
    for (int mt = 0; mt < 4; mt++)
#pragma unroll
        for (int nt = 0; nt < 4; nt++)
#pragma unroll
            for (int r = 0; r < 4; r++) acc[mt][nt][r] = 0.f;

    load_chunk(0, 0); CP_COMMIT();
    load_chunk(1, 1); CP_COMMIT();

    for (int i = 0; i < NCH; i++) {
        CP_WAIT1();
        __syncthreads();
        if (i + 2 < NCH) load_chunk(i + 2, (i + 2) % 3);
        CP_COMMIT();

        const int st = i % 3;
        const float* As = smA + st * STG_FLOATS;
        const float* Bs = smB + st * STG_FLOATS;
#pragma unroll
        for (int kk = 0; kk < 4; kk++) {
            uint32_t bf[4][2];
#pragma unroll
            for (int nt = 0; nt < 4; nt++) {
                // permuted: (b0,b1) = orig k {qcol, qcol+4} now adjacent
                float2 bv = *(const float2*)(Bs + (wn8 + nt * 32 + qrow) * PITCH + kk * 8 + 2 * qcol);
                bf[nt][0] = __float_as_uint(bv.x);
                bf[nt][1] = __float_as_uint(bv.y);
            }
#pragma unroll
            for (int mt = 0; mt < 4; mt++) {
                const float* ap = As + (wm64 + mt * 16 + qrow) * PITCH + kk * 8 + 2 * qcol;
                float2 alo = *(const float2*)ap;               // a0 (k=qcol), a2 (k=qcol+4)
                float2 ahi = *(const float2*)(ap + 8 * PITCH); // a1, a3 (row+8)
                uint32_t af[4];
                af[0] = __float_as_uint(alo.x);
                af[1] = __float_as_uint(ahi.x);
                af[2] = __float_as_uint(alo.y);
                af[3] = __float_as_uint(ahi.y);
#pragma unroll
                for (int nt = 0; nt < 4; nt++) MMA_TF32(acc[mt][nt], af, bf[nt]);
            }
        }
    }

    // ---------------- epilogue ----------------
#pragma unroll
    for (int mt = 0; mt < 4; mt++) {
#pragma unroll
        for (int r = 0; r < 4; r++) {
            const int row = wm64 + mt * 16 + qrow + (r >> 1) * 8;
            const int m = m0 + row;
            const int b = m >> 12;
            const int s = m & (S_ - 1);
            const int cc = 2 * qcol + (r & 1);

            if (MODE == 0) {
#pragma unroll
                for (int nt = 0; nt < 4; nt++) {
                    int col = wn8 + nt * 32 + cc;
                    out[(size_t)m * D_ + n0 + col] = acc[mt][nt][r] + bias[n0 + col];
                }
            } else if (MODE == 3) {
#pragma unroll
                for (int nt = 0; nt < 4; nt++) {
                    int col = wn8 + nt * 32 + cc;
                    int h = (n0 + col) >> 6, e = col & 63;
                    g_V[(((size_t)b * H_ + h) * S_ + s) * HD_ + e] =
                        acc[mt][nt][r] + bias[n0 + col];
                }
            } else {
                float* dstb = (MODE == 1) ? g_Q : g_K;
#pragma unroll
                for (int half = 0; half < 2; half++) {
                    const int p = half * 2;
                    const int h = (n0 >> 6) + half;
                    const int j = wn8 + cc;                      // 0..31
                    float x1 = acc[mt][p][r]     + bias[h * HD_ + j];
                    float x2 = acc[mt][p + 1][r] + bias[h * HD_ + j + 32];
                    float c1 = cs[s * HD_ + j],      s1 = sn[s * HD_ + j];
                    float c2 = cs[s * HD_ + j + 32], s2 = sn[s * HD_ + j + 32];
                    float r1 = x1 * c1 - x2 * s1;
                    float r2 = x2 * c2 + x1 * s2;
                    r1 = (r1 > 0.f) ? (r1 + 1.f) : expf(r1);
                    r2 = (r2 > 0.f) ? (r2 + 1.f) : expf(r2);
                    float* d = dstb + (((size_t)b * H_ + h) * S_ + s) * HD_;
                    d[j]      = fmaxf(r1, 0.01f);
                    d[j + 32] = fmaxf(r2, 0.01f);
                }
            }
        }
    }
}

// ---------------------------------------------------------------------------
// KV[bh][d][e] = sum_s K[bh][s][d] * V[bh][s][e]; KS[bh][d] = sum_s K
// ---------------------------------------------------------------------------
__global__ __launch_bounds__(128)
void kv_kernel()
{
    __shared__ __align__(16) float Ks[16 * 64];
    __shared__ __align__(16) float Vs[16 * 64];
    const int t  = threadIdx.x;
    const int bh = blockIdx.y;
    const int sp = blockIdx.x;
    const int d0 = (t >> 4) * 8;
    const int e0 = (t & 15) * 4;
    const int schunk = S_ / SPLIT_;
    const size_t base = ((size_t)bh * S_ + (size_t)sp * schunk) * HD_;

    float acc[8][4];
    float ks[8];
#pragma unroll
    for (int i = 0; i < 8; i++) {
        ks[i] = 0.f;
#pragma unroll
        for (int j = 0; j < 4; j++) acc[i][j] = 0.f;
    }

    for (int sc = 0; sc < schunk; sc += 16) {
        const float4* srk = (const float4*)(g_K + base + (size_t)sc * HD_);
        const float4* srv = (const float4*)(g_V + base + (size_t)sc * HD_);
        __syncthreads();
#pragma unroll
        for (int i = 0; i < 2; i++) {
            ((float4*)Ks)[t + i * 128] = srk[t + i * 128];
            ((float4*)Vs)[t + i * 128] = srv[t + i * 128];
        }
        __syncthreads();
#pragma unroll
        for (int k = 0; k < 16; k++) {
            float4 ka = *(const float4*)&Ks[k * 64 + d0];
            float4 kb = *(const float4*)&Ks[k * 64 + d0 + 4];
            float4 va = *(const float4*)&Vs[k * 64 + e0];
            float a[8] = {ka.x, ka.y, ka.z, ka.w, kb.x, kb.y, kb.z, kb.w};
            float v[4] = {va.x, va.y, va.z, va.w};
#pragma unroll
            for (int i = 0; i < 8; i++)
#pragma unroll
                for (int j = 0; j < 4; j++)
                    acc[i][j] = fmaf(a[i], v[j], acc[i][j]);
            if (e0 == 0) {
#pragma unroll
                for (int i = 0; i < 8; i++) ks[i] += a[i];
            }
        }
    }
    const size_t pb = ((size_t)bh * SPLIT_ + sp) * (HD_ * HD_);
#pragma unroll
    for (int i = 0; i < 8; i++)
        *(float4*)&g_KVpart[pb + (d0 + i) * HD_ + e0] =
            make_float4(acc[i][0], acc[i][1], acc[i][2], acc[i][3]);
    if (e0 == 0) {
        const size_t kb2 = ((size_t)bh * SPLIT_ + sp) * HD_;
#pragma unroll
        for (int i = 0; i < 8; i++) g_KSpart[kb2 + d0 + i] = ks[i];
    }
}

__global__ void kv_reduce()
{
    const int N1 = BH_ * HD_ * HD_;
    int g = blockIdx.x * blockDim.x + threadIdx.x;
    if (g < N1) {
        int bh  = g >> 12;
        int idx = g & (HD_ * HD_ - 1);
        float s = 0.f;
#pragma unroll
        for (int p = 0; p < SPLIT_; p++)
            s += g_KVpart[((size_t)bh * SPLIT_ + p) * (HD_ * HD_) + idx];
        g_KV[g] = s;
    } else if (g < N1 + BH_ * HD_) {
        int g2 = g - N1;
        int bh = g2 >> 6, d = g2 & 63;
        float s = 0.f;
#pragma unroll
        for (int p = 0; p < SPLIT_; p++)
            s += g_KSpart[((size_t)bh * SPLIT_ + p) * HD_ + d];
        g_KS[g2] = s;
    }
}

// ---------------------------------------------------------------------------
// out = (Q . KV) / clip(Q . KSum); writes g_O rounded to tf32 AND k-permuted
// (within each 8-group of the feature dim) so the out-proj GEMM reads it raw.
// ---------------------------------------------------------------------------
__global__ __launch_bounds__(128)
void apply_kernel()
{
    __shared__ __align__(16) float Qs[64][72];
    __shared__ __align__(16) float KVs[64 * 64];
    __shared__ float KSs[64];

    const int t  = threadIdx.x;
    const int bh = blockIdx.y;
    const int b  = bh >> 4;
    const int h  = bh & 15;
    const int s0 = blockIdx.x * 64;

    {
        const float4* src = (const float4*)(g_KV + (size_t)bh * (HD_ * HD_));
#pragma unroll
        for (int i = 0; i < 8; i++)
            ((float4*)KVs)[t + i * 128] = src[t + i * 128];
        if (t < 64) KSs[t] = g_KS[bh * HD_ + t];
    }
    {
        const float4* src = (const float4*)(g_Q + ((size_t)bh * S_ + s0) * HD_);
#pragma unroll
        for (int i = 0; i < 8; i++) {
            int p = t + i * 128;
            float4 v = src[p];
            int row = p >> 4, d = (p & 15) * 4;
            Qs[d][row] = v.x; Qs[d + 1][row] = v.y;
            Qs[d + 2][row] = v.z; Qs[d + 3][row] = v.w;
        }
    }
    __syncthreads();

    const int ty = t >> 3, tx = t & 7;
    const int e0 = tx * 8;
    float acc[4][8], an[4];
#pragma unroll
    for (int i = 0; i < 4; i++) {
        an[i] = 0.f;
#pragma unroll
        for (int j = 0; j < 8; j++) acc[i][j] = 0.f;
    }

#pragma unroll 8
    for (int d = 0; d < 64; d++) {
        float4 q  = *(const float4*)&Qs[d][ty * 4];
        float4 k0 = *(const float4*)&KVs[d * 64 + e0];
        float4 k1 = *(const float4*)&KVs[d * 64 + e0 + 4];
        float ksd = KSs[d];
        float a[4] = {q.x, q.y, q.z, q.w};
        float v[8] = {k0.x, k0.y, k0.z, k0.w, k1.x, k1.y, k1.z, k1.w};
#pragma unroll
        for (int i = 0; i < 4; i++) {
#pragma unroll
            for (int j = 0; j < 8; j++)
                acc[i][j] = fmaf(a[i], v[j], acc[i][j]);
            an[i] = fmaf(a[i], ksd, an[i]);
        }
    }

#pragma unroll
    for (int i = 0; i < 4; i++) {
        int s = s0 + ty * 4 + i;
        float inv = 1.0f / (fmaxf(an[i], 1.0f) + 1e-6f);
        float* dst = &g_O[((size_t)b * S_ + s) * D_ + h * HD_ + e0];
        // k-permuted store: {o0,o4,o1,o5},{o2,o6,o3,o7}
        *(float4*)dst = make_float4(rtf32(acc[i][0] * inv), rtf32(acc[i][4] * inv),
                                    rtf32(acc[i][1] * inv), rtf32(acc[i][5] * inv));
        *(float4*)(dst + 4) = make_float4(rtf32(acc[i][2] * inv), rtf32(acc[i][6] * inv),
                                          rtf32(acc[i][3] * inv), rtf32(acc[i][7] * inv));
    }
}

// ---------------------------------------------------------------------------
extern "C" void kernel_launch(void* const* d_in, const int* in_sizes, int n_in,
                              void* d_out, int out_size)
{
    (void)in_sizes; (void)n_in; (void)out_size;
    const float* query = (const float*)d_in[0];
    const float* key   = (const float*)d_in[1];
    const float* value = (const float*)d_in[2];
    const float* cosp  = (const float*)d_in[3];
    const float* sinp  = (const float*)d_in[4];
    const float* Wq = (const float*)d_in[5];
    const float* bq = (const float*)d_in[6];
    const float* Wk = (const float*)d_in[7];
    const float* bk = (const float*)d_in[8];
    const float* Wv = (const float*)d_in[9];
    const float* bv = (const float*)d_in[10];
    const float* Wo = (const float*)d_in[11];
    const float* bo = (const float*)d_in[12];
    float* out = (float*)d_out;

    float* pAr = nullptr; float* pWr = nullptr;
    cudaGetSymbolAddress((void**)&pAr, g_Ar);
    cudaGetSymbolAddress((void**)&pWr, g_Wr);

    cudaFuncSetAttribute(gemm_tc<0>, cudaFuncAttributeMaxDynamicSharedMemorySize, SMEM_BYTES);
    cudaFuncSetAttribute(gemm_tc<1>, cudaFuncAttributeMaxDynamicSharedMemorySize, SMEM_BYTES);
    cudaFuncSetAttribute(gemm_tc<2>, cudaFuncAttributeMaxDynamicSharedMemorySize, SMEM_BYTES);
    cudaFuncSetAttribute(gemm_tc<3>, cudaFuncAttributeMaxDynamicSharedMemorySize, SMEM_BYTES);

    const int nA8 = M_ * D_ / 8;      // 8-groups in activations
    const int nW8 = D_ * D_ / 8;
    dim3 gt(D_ / TN, M_ / TM);        // (8, 128)

    round_perm_kernel<<<(nA8 + 255) / 256, 256>>>((const float4*)query, (float4*)pAr, nA8);
    round_perm_kernel<<<(nW8 + 255) / 256, 256>>>((const float4*)Wq, (float4*)pWr, nW8);
    gemm_tc<1><<<gt, 256, SMEM_BYTES>>>(pAr, pWr, bq, nullptr, cosp, sinp);

    round_perm_kernel<<<(nA8 + 255) / 256, 256>>>((const float4*)key, (float4*)pAr, nA8);
    round_perm_kernel<<<(nW8 + 255) / 256, 256>>>((const float4*)Wk, (float4*)pWr, nW8);
    gemm_tc<2><<<gt, 256, SMEM_BYTES>>>(pAr, pWr, bk, nullptr, cosp, sinp);

    round_perm_kernel<<<(nA8 + 255) / 256, 256>>>((const float4*)value, (float4*)pAr, nA8);
    round_perm_kernel<<<(nW8 + 255) / 256, 256>>>((const float4*)Wv, (float4*)pWr, nW8);
    gemm_tc<3><<<gt, 256, SMEM_BYTES>>>(pAr, pWr, bv, nullptr, cosp, sinp);

    kv_kernel<<<dim3(SPLIT_, BH_), 128>>>();
    kv_reduce<<<(BH_ * HD_ * HD_ + BH_ * HD_ + 255) / 256, 256>>>();
    apply_kernel<<<dim3(S_ / 64, BH_), 128>>>();

    round_perm_kernel<<<(nW8 + 255) / 256, 256>>>((const float4*)Wo, (float4*)pWr, nW8);
    gemm_tc<0><<<gt, 256, SMEM_BYTES>>>(nullptr, pWr, bo, out, nullptr, nullptr);
}

// round 6
// speedup vs baseline: 4.3218x; 1.5173x over previous
#include <cuda_runtime.h>
#include <cuda_fp16.h>
#include <cstdint>
#include <math.h>

#define B_ 4
#define S_ 4096
#define D_ 1024
#define H_ 16
#define HD_ 64
#define M_ (B_*S_)          // 16384
#define BH_ (B_*H_)         // 64
#define SPLIT_ 16

// GEMM tiling (fp16 mma.sync m16n8k16, fp32 accumulate)
#define TM 128
#define TN 128
#define BKH 64                      // halves per K-chunk = 128B row
#define NCH (D_/BKH)                // 16 chunks
#define PITCHB 160                  // bytes per smem row (128 data + 32 pad)
#define STG_BYTES (128*PITCHB)      // 20480 per operand per stage
#define SMEM_BYTES (6*STG_BYTES)    // 3 stages x (A+B) = 122880 B

// ---------------- scratch (device globals; no allocation) ----------------
// Half buffers hold PAIR-PERMUTED data: within each 16-element group of the
// contraction dim, half-pairs are reordered {0,4,1,5,2,6,3,7} so each mma
// fragment's two k-pairs (orig j and j+4) are adjacent -> one LDS.64.
__device__ __align__(16) float  g_Q[(size_t)M_ * D_];   // [b,h,s,d] fp32
__device__ __align__(16) float  g_K[(size_t)M_ * D_];
__device__ __align__(16) float  g_V[(size_t)M_ * D_];
__device__ __align__(16) __half g_O[(size_t)M_ * D_];   // [b,s,h*64+e], fp16+perm
__device__ __align__(16) __half g_Ah[(size_t)M_ * D_];  // fp16+perm activations
__device__ __align__(16) __half g_Wh[(size_t)D_ * D_];  // fp16+perm weights
__device__ __align__(16) float  g_KVpart[(size_t)BH_ * SPLIT_ * HD_ * HD_];
__device__ __align__(16) float  g_KSpart[(size_t)BH_ * SPLIT_ * HD_];
__device__ __align__(16) float  g_KV[(size_t)BH_ * HD_ * HD_];
__device__ __align__(16) float  g_KS[(size_t)BH_ * HD_];

// ---------------- helpers ----------------
__device__ __forceinline__ uint32_t smem_u32(const void* p) {
    uint32_t a;
    asm("{ .reg .u64 t; cvta.to.shared.u64 t, %1; cvt.u32.u64 %0, t; }" : "=r"(a) : "l"(p));
    return a;
}
#define CP16(dst, src) asm volatile("cp.async.cg.shared.global [%0], [%1], 16;" :: "r"(dst), "l"(src))
#define CP_COMMIT()    asm volatile("cp.async.commit_group;" ::: "memory")
#define CP_WAIT1()     asm volatile("cp.async.wait_group 1;" ::: "memory")

#define MMA_F16(c, a, b) \
    asm volatile("mma.sync.aligned.m16n8k16.row.col.f32.f16.f16.f32 " \
        "{%0,%1,%2,%3}, {%4,%5,%6,%7}, {%8,%9}, {%0,%1,%2,%3};" \
        : "+f"((c)[0]), "+f"((c)[1]), "+f"((c)[2]), "+f"((c)[3]) \
        : "r"((a)[0]), "r"((a)[1]), "r"((a)[2]), "r"((a)[3]), \
          "r"((b)[0]), "r"((b)[1]))

__device__ __forceinline__ uint32_t pack_h2(float lo, float hi) {
    __half2 h = __floats2half2_rn(lo, hi);
    return *reinterpret_cast<uint32_t*>(&h);
}

// ---------------------------------------------------------------------------
// fp32 -> fp16 RN conversion + pair-permute within each 16-element group.
// Per group of 16 floats, output half-pairs in order {P0,P4,P1,P5,P2,P6,P3,P7}.
// One thread handles one group (reads 64B, writes 32B).
// ---------------------------------------------------------------------------
__global__ void conv_half_kernel(const float4* __restrict__ src, uint4* __restrict__ dst, int n16)
{
    int i = blockIdx.x * blockDim.x + threadIdx.x;
    if (i < n16) {
        float4 v0 = src[4 * i], v1 = src[4 * i + 1], v2 = src[4 * i + 2], v3 = src[4 * i + 3];
        uint4 o0, o1;
        o0.x = pack_h2(v0.x, v0.y);   // f0 f1
        o0.y = pack_h2(v2.x, v2.y);   // f8 f9
        o0.z = pack_h2(v0.z, v0.w);   // f2 f3
        o0.w = pack_h2(v2.z, v2.w);   // f10 f11
        o1.x = pack_h2(v1.x, v1.y);   // f4 f5
        o1.y = pack_h2(v3.x, v3.y);   // f12 f13
        o1.z = pack_h2(v1.z, v1.w);   // f6 f7
        o1.w = pack_h2(v3.z, v3.w);   // f14 f15
        dst[2 * i] = o0;
        dst[2 * i + 1] = o1;
    }
}

// ---------------------------------------------------------------------------
// fp16 mma.sync GEMM  C = A @ W^T + bias  (A:[16384,1024]h, W:[1024,1024]h)
// 128x128 tile, BK=64 halves, 3-stage cp.async, warp tile 64x32 (n-tiles at
// {0,32,64,96} so RoPE pairs (j, j+32) stay in one thread).
// MODE: 0 plain -> out ; 1 rope+elu -> g_Q ; 2 rope+elu -> g_K ; 3 bias -> g_V
// ---------------------------------------------------------------------------
template<int MODE>
__global__ __launch_bounds__(256, 1)
void gemm_tc(const __half* __restrict__ A, const __half* __restrict__ W,
             const float* __restrict__ bias, float* __restrict__ out,
             const float* __restrict__ cs, const float* __restrict__ sn)
{
    extern __shared__ __align__(16) char sm[];
    const int tid = threadIdx.x;
    const int n0  = blockIdx.x * TN;
    const int m0  = blockIdx.y * TM;
    const __half* __restrict__ Ap = (MODE == 0) ? (const __half*)g_O : A;

    const int lane   = tid & 31;
    const int wid    = tid >> 5;
    const int wm64   = (wid & 1) * 64;
    const int wn8    = (wid >> 1) * 8;
    const int qrow   = lane >> 2;
    const int qcol   = lane & 3;

    const uint32_t sm_u = smem_u32(sm);

    auto load_chunk = [&](int ch, int st) {
        const int k0 = ch * BKH;
        const uint32_t aB = sm_u + (uint32_t)st * 2 * STG_BYTES;
        const uint32_t bB = aB + STG_BYTES;
#pragma unroll
        for (int j = 0; j < 4; j++) {                 // A: 128 rows x 8 x 16B
            int q = tid + j * 256, row = q >> 3, seg = q & 7;
            CP16(aB + (uint32_t)(row * PITCHB + seg * 16),
                 Ap + (size_t)(m0 + row) * D_ + k0 + seg * 8);
        }
#pragma unroll
        for (int j = 0; j < 4; j++) {                 // B(W): 128 rows x 8 x 16B
            int q = tid + j * 256, row = q >> 3, seg = q & 7;
            CP16(bB + (uint32_t)(row * PITCHB + seg * 16),
                 W + (size_t)(n0 + row) * D_ + k0 + seg * 8);
        }
    };

    float acc[4][4][4];
#pragma unroll
    for (int mt = 0; mt < 4; mt++)
#pragma unroll
        for (int nt = 0; nt < 4; nt++)
#pragma unroll
            for (int r = 0; r < 4; r++) acc[mt][nt][r] = 0.f;

    load_chunk(0, 0); CP_COMMIT();
    load_chunk(1, 1); CP_COMMIT();

    for (int i = 0; i < NCH; i++) {
        CP_WAIT1();
        __syncthreads();
        if (i + 2 < NCH) load_chunk(i + 2, (i + 2) % 3);
        CP_COMMIT();

        const int st = i % 3;
        const char* As = sm + (size_t)st * 2 * STG_BYTES;
        const char* Bs = As + STG_BYTES;
#pragma unroll
        for (int kk = 0; kk < 4; kk++) {              // 4 x k=16 per chunk
            uint32_t bf[4][2];
#pragma unroll
            for (int nt = 0; nt < 4; nt++) {
                uint2 bv = *(const uint2*)(Bs + (wn8 + nt * 32 + qrow) * PITCHB + kk * 32 + 8 * qcol);
                bf[nt][0] = bv.x;    // k = 2qcol..2qcol+1
                bf[nt][1] = bv.y;    // k+8
            }
#pragma unroll
            for (int mt = 0; mt < 4; mt++) {
                const char* ap = As + (wm64 + mt * 16 + qrow) * PITCHB + kk * 32 + 8 * qcol;
                uint2 alo = *(const uint2*)ap;                  // row r:   a0, a2
                uint2 ahi = *(const uint2*)(ap + 8 * PITCHB);   // row r+8: a1, a3
                uint32_t af[4] = {alo.x, ahi.x, alo.y, ahi.y};
#pragma unroll
                for (int nt = 0; nt < 4; nt++) MMA_F16(acc[mt][nt], af, bf[nt]);
            }
        }
    }

    // ---------------- epilogue ----------------
#pragma unroll
    for (int mt = 0; mt < 4; mt++) {
#pragma unroll
        for (int r = 0; r < 4; r++) {
            const int row = wm64 + mt * 16 + qrow + (r >> 1) * 8;
            const int m = m0 + row;
            const int b = m >> 12;
            const int s = m & (S_ - 1);
            const int cc = 2 * qcol + (r & 1);

            if (MODE == 0) {
#pragma unroll
                for (int nt = 0; nt < 4; nt++) {
                    int col = wn8 + nt * 32 + cc;
                    out[(size_t)m * D_ + n0 + col] = acc[mt][nt][r] + bias[n0 + col];
                }
            } else if (MODE == 3) {
#pragma unroll
                for (int nt = 0; nt < 4; nt++) {
                    int col = wn8 + nt * 32 + cc;
                    int h = (n0 + col) >> 6, e = col & 63;
                    g_V[(((size_t)b * H_ + h) * S_ + s) * HD_ + e] =
                        acc[mt][nt][r] + bias[n0 + col];
                }
            } else {
                float* dstb = (MODE == 1) ? g_Q : g_K;
#pragma unroll
                for (int half = 0; half < 2; half++) {
                    const int p = half * 2;
                    const int h = (n0 >> 6) + half;
                    const int j = wn8 + cc;                      // 0..31
                    float x1 = acc[mt][p][r]     + bias[h * HD_ + j];
                    float x2 = acc[mt][p + 1][r] + bias[h * HD_ + j + 32];
                    float c1 = cs[s * HD_ + j],      s1 = sn[s * HD_ + j];
                    float c2 = cs[s * HD_ + j + 32], s2 = sn[s * HD_ + j + 32];
                    float r1 = x1 * c1 - x2 * s1;
                    float r2 = x2 * c2 + x1 * s2;
                    r1 = (r1 > 0.f) ? (r1 + 1.f) : expf(r1);
                    r2 = (r2 > 0.f) ? (r2 + 1.f) : expf(r2);
                    float* d = dstb + (((size_t)b * H_ + h) * S_ + s) * HD_;
                    d[j]      = fmaxf(r1, 0.01f);
                    d[j + 32] = fmaxf(r2, 0.01f);
                }
            }
        }
    }
}

// ---------------------------------------------------------------------------
// KV[bh][d][e] = sum_s K[bh][s][d] * V[bh][s][e]; KS[bh][d] = sum_s K
// ---------------------------------------------------------------------------
__global__ __launch_bounds__(128)
void kv_kernel()
{
    __shared__ __align__(16) float Ks[16 * 64];
    __shared__ __align__(16) float Vs[16 * 64];
    const int t  = threadIdx.x;
    const int bh = blockIdx.y;
    const int sp = blockIdx.x;
    const int d0 = (t >> 4) * 8;
    const int e0 = (t & 15) * 4;
    const int schunk = S_ / SPLIT_;
    const size_t base = ((size_t)bh * S_ + (size_t)sp * schunk) * HD_;

    float acc[8][4];
    float ks[8];
#pragma unroll
    for (int i = 0; i < 8; i++) {
        ks[i] = 0.f;
#pragma unroll
        for (int j = 0; j < 4; j++) acc[i][j] = 0.f;
    }

    for (int sc = 0; sc < schunk; sc += 16) {
        const float4* srk = (const float4*)(g_K + base + (size_t)sc * HD_);
        const float4* srv = (const float4*)(g_V + base + (size_t)sc * HD_);
        __syncthreads();
#pragma unroll
        for (int i = 0; i < 2; i++) {
            ((float4*)Ks)[t + i * 128] = srk[t + i * 128];
            ((float4*)Vs)[t + i * 128] = srv[t + i * 128];
        }
        __syncthreads();
#pragma unroll
        for (int k = 0; k < 16; k++) {
            float4 ka = *(const float4*)&Ks[k * 64 + d0];
            float4 kb = *(const float4*)&Ks[k * 64 + d0 + 4];
            float4 va = *(const float4*)&Vs[k * 64 + e0];
            float a[8] = {ka.x, ka.y, ka.z, ka.w, kb.x, kb.y, kb.z, kb.w};
            float v[4] = {va.x, va.y, va.z, va.w};
#pragma unroll
            for (int i = 0; i < 8; i++)
#pragma unroll
                for (int j = 0; j < 4; j++)
                    acc[i][j] = fmaf(a[i], v[j], acc[i][j]);
            if (e0 == 0) {
#pragma unroll
                for (int i = 0; i < 8; i++) ks[i] += a[i];
            }
        }
    }
    const size_t pb = ((size_t)bh * SPLIT_ + sp) * (HD_ * HD_);
#pragma unroll
    for (int i = 0; i < 8; i++)
        *(float4*)&g_KVpart[pb + (d0 + i) * HD_ + e0] =
            make_float4(acc[i][0], acc[i][1], acc[i][2], acc[i][3]);
    if (e0 == 0) {
        const size_t kb2 = ((size_t)bh * SPLIT_ + sp) * HD_;
#pragma unroll
        for (int i = 0; i < 8; i++) g_KSpart[kb2 + d0 + i] = ks[i];
    }
}

__global__ void kv_reduce()
{
    const int N1 = BH_ * HD_ * HD_;
    int g = blockIdx.x * blockDim.x + threadIdx.x;
    if (g < N1) {
        int bh  = g >> 12;
        int idx = g & (HD_ * HD_ - 1);
        float s = 0.f;
#pragma unroll
        for (int p = 0; p < SPLIT_; p++)
            s += g_KVpart[((size_t)bh * SPLIT_ + p) * (HD_ * HD_) + idx];
        g_KV[g] = s;
    } else if (g < N1 + BH_ * HD_) {
        int g2 = g - N1;
        int bh = g2 >> 6, d = g2 & 63;
        float s = 0.f;
#pragma unroll
        for (int p = 0; p < SPLIT_; p++)
            s += g_KSpart[((size_t)bh * SPLIT_ + p) * HD_ + d];
        g_KS[g2] = s;
    }
}

// ---------------------------------------------------------------------------
// out = (Q . KV) / clip(Q . KSum); writes g_O as fp16, pair-permuted within
// each 16-col group so the out-proj GEMM reads it directly.
// ---------------------------------------------------------------------------
__global__ __launch_bounds__(128)
void apply_kernel()
{
    __shared__ __align__(16) float Qs[64][72];
    __shared__ __align__(16) float KVs[64 * 64];
    __shared__ float KSs[64];

    const int t  = threadIdx.x;
    const int bh = blockIdx.y;
    const int b  = bh >> 4;
    const int h  = bh & 15;
    const int s0 = blockIdx.x * 64;

    {
        const float4* src = (const float4*)(g_KV + (size_t)bh * (HD_ * HD_));
#pragma unroll
        for (int i = 0; i < 8; i++)
            ((float4*)KVs)[t + i * 128] = src[t + i * 128];
        if (t < 64) KSs[t] = g_KS[bh * HD_ + t];
    }
    {
        const float4* src = (const float4*)(g_Q + ((size_t)bh * S_ + s0) * HD_);
#pragma unroll
        for (int i = 0; i < 8; i++) {
            int p = t + i * 128;
            float4 v = src[p];
            int row = p >> 4, d = (p & 15) * 4;
            Qs[d][row] = v.x; Qs[d + 1][row] = v.y;
            Qs[d + 2][row] = v.z; Qs[d + 3][row] = v.w;
        }
    }
    __syncthreads();

    const int ty = t >> 3, tx = t & 7;
    const int e0 = tx * 8;
    float acc[4][8], an[4];
#pragma unroll
    for (int i = 0; i < 4; i++) {
        an[i] = 0.f;
#pragma unroll
        for (int j = 0; j < 8; j++) acc[i][j] = 0.f;
    }

#pragma unroll 8
    for (int d = 0; d < 64; d++) {
        float4 q  = *(const float4*)&Qs[d][ty * 4];
        float4 k0 = *(const float4*)&KVs[d * 64 + e0];
        float4 k1 = *(const float4*)&KVs[d * 64 + e0 + 4];
        float ksd = KSs[d];
        float a[4] = {q.x, q.y, q.z, q.w};
        float v[8] = {k0.x, k0.y, k0.z, k0.w, k1.x, k1.y, k1.z, k1.w};
#pragma unroll
        for (int i = 0; i < 4; i++) {
#pragma unroll
            for (int j = 0; j < 8; j++)
                acc[i][j] = fmaf(a[i], v[j], acc[i][j]);
            an[i] = fmaf(a[i], ksd, an[i]);
        }
    }

#pragma unroll
    for (int i = 0; i < 4; i++) {
        int s = s0 + ty * 4 + i;
        float inv = 1.0f / (fmaxf(an[i], 1.0f) + 1e-6f);
        // pair-permuted fp16 store: this thread's 4 pairs land at group slots
        // {0,2,4,6} (tx even) or {1,3,5,7} (tx odd) of the 16-col group.
        const size_t rowbase = ((size_t)b * S_ + s) * D_;
        const int colgroup = h * HD_ + e0 - 8 * (tx & 1);   // group-aligned base col
        __half2* dst = (__half2*)(g_O + rowbase + colgroup + 2 * (tx & 1));
#pragma unroll
        for (int p = 0; p < 4; p++) {
            __half2 hv = __floats2half2_rn(acc[i][2 * p] * inv, acc[i][2 * p + 1] * inv);
            dst[2 * p] = hv;      // stride 4 halves = 2 half2 slots
        }
    }
}

// ---------------------------------------------------------------------------
extern "C" void kernel_launch(void* const* d_in, const int* in_sizes, int n_in,
                              void* d_out, int out_size)
{
    (void)in_sizes; (void)n_in; (void)out_size;
    const float* query = (const float*)d_in[0];
    const float* key   = (const float*)d_in[1];
    const float* value = (const float*)d_in[2];
    const float* cosp  = (const float*)d_in[3];
    const float* sinp  = (const float*)d_in[4];
    const float* Wq = (const float*)d_in[5];
    const float* bq = (const float*)d_in[6];
    const float* Wk = (const float*)d_in[7];
    const float* bk = (const float*)d_in[8];
    const float* Wv = (const float*)d_in[9];
    const float* bv = (const float*)d_in[10];
    const float* Wo = (const float*)d_in[11];
    const float* bo = (const float*)d_in[12];
    float* out = (float*)d_out;

    __half* pAh = nullptr; __half* pWh = nullptr;
    cudaGetSymbolAddress((void**)&pAh, g_Ah);
    cudaGetSymbolAddress((void**)&pWh, g_Wh);

    cudaFuncSetAttribute(gemm_tc<0>, cudaFuncAttributeMaxDynamicSharedMemorySize, SMEM_BYTES);
    cudaFuncSetAttribute(gemm_tc<1>, cudaFuncAttributeMaxDynamicSharedMemorySize, SMEM_BYTES);
    cudaFuncSetAttribute(gemm_tc<2>, cudaFuncAttributeMaxDynamicSharedMemorySize, SMEM_BYTES);
    cudaFuncSetAttribute(gemm_tc<3>, cudaFuncAttributeMaxDynamicSharedMemorySize, SMEM_BYTES);

    const int nA16 = M_ * D_ / 16;    // 16-element groups
    const int nW16 = D_ * D_ / 16;
    dim3 gt(D_ / TN, M_ / TM);        // (8, 128)

    conv_half_kernel<<<(nA16 + 255) / 256, 256>>>((const float4*)query, (uint4*)pAh, nA16);
    conv_half_kernel<<<(nW16 + 255) / 256, 256>>>((const float4*)Wq, (uint4*)pWh, nW16);
    gemm_tc<1><<<gt, 256, SMEM_BYTES>>>(pAh, pWh, bq, nullptr, cosp, sinp);

    conv_half_kernel<<<(nA16 + 255) / 256, 256>>>((const float4*)key, (uint4*)pAh, nA16);
    conv_half_kernel<<<(nW16 + 255) / 256, 256>>>((const float4*)Wk, (uint4*)pWh, nW16);
    gemm_tc<2><<<gt, 256, SMEM_BYTES>>>(pAh, pWh, bk, nullptr, cosp, sinp);

    conv_half_kernel<<<(nA16 + 255) / 256, 256>>>((const float4*)value, (uint4*)pAh, nA16);
    conv_half_kernel<<<(nW16 + 255) / 256, 256>>>((const float4*)Wv, (uint4*)pWh, nW16);
    gemm_tc<3><<<gt, 256, SMEM_BYTES>>>(pAh, pWh, bv, nullptr, cosp, sinp);

    kv_kernel<<<dim3(SPLIT_, BH_), 128>>>();
    kv_reduce<<<(BH_ * HD_ * HD_ + BH_ * HD_ + 255) / 256, 256>>>();
    apply_kernel<<<dim3(S_ / 64, BH_), 128>>>();

    conv_half_kernel<<<(nW16 + 255) / 256, 256>>>((const float4*)Wo, (uint4*)pWh, nW16);
    gemm_tc<0><<<gt, 256, SMEM_BYTES>>>(nullptr, pWh, bo, out, nullptr, nullptr);
}

// round 9
// speedup vs baseline: 5.1370x; 1.1886x over previous
#include <cuda_runtime.h>
#include <cuda_fp16.h>
#include <cstdint>
#include <math.h>

#define B_ 4
#define S_ 4096
#define D_ 1024
#define H_ 16
#define HD_ 64
#define M_ (B_*S_)          // 16384
#define BH_ (B_*H_)         // 64
#define SPLIT_ 16

// GEMM tiling (fp16 mma.sync m16n8k16, fp32 accumulate)
#define TM 128
#define TN 128
#define BKH 64                      // halves per K-chunk = 128B row
#define NCH (D_/BKH)                // 16 chunks
#define PITCHB 160                  // bytes per smem row (128 data + 32 pad)
#define STG_BYTES (128*PITCHB)
#define SMEM_BYTES (6*STG_BYTES)    // 122880 B

// mid-section smem pitch: 144B per 72-half row -> conflict-free ldmatrix
#define MPITCH 144

// ---------------- scratch (device globals; no allocation) ----------------
__device__ __align__(16) __half g_Qh[(size_t)M_ * D_];  // [bh][s][d] fp16
__device__ __align__(16) __half g_Kh[(size_t)M_ * D_];
__device__ __align__(16) __half g_Vh[(size_t)M_ * D_];
__device__ __align__(16) __half g_O[(size_t)M_ * D_];   // [b,s,1024] fp16+perm
__device__ __align__(16) __half g_Ah[3][(size_t)M_ * D_]; // fp16+perm activations
__device__ __align__(16) __half g_Wh[4][(size_t)D_ * D_]; // fp16+perm weights
__device__ __align__(16) float  g_KVpart[(size_t)BH_ * SPLIT_ * HD_ * 72]; // [..][d][72]
__device__ __align__(16) __half g_KVh[(size_t)BH_ * HD_ * 72]; // [bh][d][72]: 0-63 KV, 64 KS, 65-71 zero

// ---------------- helpers ----------------
__device__ __forceinline__ uint32_t smem_u32(const void* p) {
    uint32_t a;
    asm("{ .reg .u64 t; cvta.to.shared.u64 t, %1; cvt.u32.u64 %0, t; }" : "=r"(a) : "l"(p));
    return a;
}
#define CP16(dst, src) asm volatile("cp.async.cg.shared.global [%0], [%1], 16;" :: "r"(dst), "l"(src))
#define CP_COMMIT()    asm volatile("cp.async.commit_group;" ::: "memory")
#define CP_WAIT1()     asm volatile("cp.async.wait_group 1;" ::: "memory")
#define CP_WAIT0()     asm volatile("cp.async.wait_group 0;" ::: "memory")

#define MMA_F16(c, a, b) \
    asm volatile("mma.sync.aligned.m16n8k16.row.col.f32.f16.f16.f32 " \
        "{%0,%1,%2,%3}, {%4,%5,%6,%7}, {%8,%9}, {%0,%1,%2,%3};" \
        : "+f"((c)[0]), "+f"((c)[1]), "+f"((c)[2]), "+f"((c)[3]) \
        : "r"((a)[0]), "r"((a)[1]), "r"((a)[2]), "r"((a)[3]), \
          "r"((b)[0]), "r"((b)[1]))

#define LDSM_X4(r0, r1, r2, r3, addr) \
    asm volatile("ldmatrix.sync.aligned.m8n8.x4.shared.b16 {%0,%1,%2,%3}, [%4];" \
        : "=r"(r0), "=r"(r1), "=r"(r2), "=r"(r3) : "r"(addr))
#define LDSM_X4_T(r0, r1, r2, r3, addr) \
    asm volatile("ldmatrix.sync.aligned.m8n8.x4.trans.shared.b16 {%0,%1,%2,%3}, [%4];" \
        : "=r"(r0), "=r"(r1), "=r"(r2), "=r"(r3) : "r"(addr))
#define LDSM_X2_T(r0, r1, addr) \
    asm volatile("ldmatrix.sync.aligned.m8n8.x2.trans.shared.b16 {%0,%1}, [%2];" \
        : "=r"(r0), "=r"(r1) : "r"(addr))

__device__ __forceinline__ uint32_t pack_h2(float lo, float hi) {
    __half2 h = __floats2half2_rn(lo, hi);
    return *reinterpret_cast<uint32_t*>(&h);
}

// ---------------------------------------------------------------------------
// fp32 -> fp16 RN + pair-permute within 16-groups: pairs out {0,4,1,5,2,6,3,7}
// ---------------------------------------------------------------------------
__device__ __forceinline__ void conv_body(const float4* __restrict__ src,
                                          uint4* __restrict__ dst, int i)
{
    float4 v0 = src[4 * i], v1 = src[4 * i + 1], v2 = src[4 * i + 2], v3 = src[4 * i + 3];
    uint4 o0, o1;
    o0.x = pack_h2(v0.x, v0.y);   o0.y = pack_h2(v2.x, v2.y);
    o0.z = pack_h2(v0.z, v0.w);   o0.w = pack_h2(v2.z, v2.w);
    o1.x = pack_h2(v1.x, v1.y);   o1.y = pack_h2(v3.x, v3.y);
    o1.z = pack_h2(v1.z, v1.w);   o1.w = pack_h2(v3.z, v3.w);
    dst[2 * i] = o0;  dst[2 * i + 1] = o1;
}

__global__ void conv_act_kernel(const float4* __restrict__ q, const float4* __restrict__ k,
                                const float4* __restrict__ v)
{
    int i = blockIdx.x * blockDim.x + threadIdx.x;
    const int n16 = M_ * D_ / 16;
    if (i < n16) {
        const float4* src = (blockIdx.y == 0) ? q : (blockIdx.y == 1) ? k : v;
        conv_body(src, (uint4*)(g_Ah[blockIdx.y]), i);
    }
}

__global__ void conv_w_kernel(const float4* __restrict__ w0, const float4* __restrict__ w1,
                              const float4* __restrict__ w2, const float4* __restrict__ w3)
{
    int i = blockIdx.x * blockDim.x + threadIdx.x;
    const int n16 = D_ * D_ / 16;
    if (i < n16) {
        const float4* src = (blockIdx.y == 0) ? w0 : (blockIdx.y == 1) ? w1
                          : (blockIdx.y == 2) ? w2 : w3;
        conv_body(src, (uint4*)(g_Wh[blockIdx.y]), i);
    }
}

// ---------------------------------------------------------------------------
// fp16 mma.sync GEMM  C = A @ W^T + bias
// MODE: 0 plain->out(f32) ; 1 rope+elu->g_Qh ; 2 rope+elu->g_Kh ; 3 bias->g_Vh
// ---------------------------------------------------------------------------
template<int MODE>
__global__ __launch_bounds__(256, 1)
void gemm_tc(const __half* __restrict__ A, const __half* __restrict__ W,
             const float* __restrict__ bias, float* __restrict__ out,
             const float* __restrict__ cs, const float* __restrict__ sn)
{
    extern __shared__ __align__(16) char sm[];
    const int tid = threadIdx.x;
    const int n0  = blockIdx.x * TN;
    const int m0  = blockIdx.y * TM;
    const __half* __restrict__ Ap = (MODE == 0) ? (const __half*)g_O : A;

    const int lane = tid & 31;
    const int wid  = tid >> 5;
    const int wm64 = (wid & 1) * 64;
    const int wn8  = (wid >> 1) * 8;
    const int qrow = lane >> 2;
    const int qcol = lane & 3;
    const uint32_t sm_u = smem_u32(sm);

    auto load_chunk = [&](int ch, int st) {
        const int k0 = ch * BKH;
        const uint32_t aB = sm_u + (uint32_t)st * 2 * STG_BYTES;
        const uint32_t bB = aB + STG_BYTES;
#pragma unroll
        for (int j = 0; j < 4; j++) {
            int q = tid + j * 256, row = q >> 3, seg = q & 7;
            CP16(aB + (uint32_t)(row * PITCHB + seg * 16),
                 Ap + (size_t)(m0 + row) * D_ + k0 + seg * 8);
        }
#pragma unroll
        for (int j = 0; j < 4; j++) {
            int q = tid + j * 256, row = q >> 3, seg = q & 7;
            CP16(bB + (uint32_t)(row * PITCHB + seg * 16),
                 W + (size_t)(n0 + row) * D_ + k0 + seg * 8);
        }
    };

    float acc[4][4][4];
#pragma unroll
    for (int mt = 0; mt < 4; mt++)
#pragma unroll
        for (int nt = 0; nt < 4; nt++)
#pragma unroll
            for (int r = 0; r < 4; r++) acc[mt][nt][r] = 0.f;

    load_chunk(0, 0); CP_COMMIT();
    load_chunk(1, 1); CP_COMMIT();

    for (int i = 0; i < NCH; i++) {
        CP_WAIT1();
        __syncthreads();
        if (i + 2 < NCH) load_chunk(i + 2, (i + 2) % 3);
        CP_COMMIT();

        const int st = i % 3;
        const char* As = sm + (size_t)st * 2 * STG_BYTES;
        const char* Bs = As + STG_BYTES;
#pragma unroll
        for (int kk = 0; kk < 4; kk++) {
            uint32_t bf[4][2];
#pragma unroll
            for (int nt = 0; nt < 4; nt++) {
                uint2 bv = *(const uint2*)(Bs + (wn8 + nt * 32 + qrow) * PITCHB + kk * 32 + 8 * qcol);
                bf[nt][0] = bv.x;  bf[nt][1] = bv.y;
            }
#pragma unroll
            for (int mt = 0; mt < 4; mt++) {
                const char* ap = As + (wm64 + mt * 16 + qrow) * PITCHB + kk * 32 + 8 * qcol;
                uint2 alo = *(const uint2*)ap;
                uint2 ahi = *(const uint2*)(ap + 8 * PITCHB);
                uint32_t af[4] = {alo.x, ahi.x, alo.y, ahi.y};
#pragma unroll
                for (int nt = 0; nt < 4; nt++) MMA_F16(acc[mt][nt], af, bf[nt]);
            }
        }
    }

    // ---------------- epilogue ----------------
#pragma unroll
    for (int mt = 0; mt < 4; mt++) {
#pragma unroll
        for (int r = 0; r < 4; r++) {
            const int row = wm64 + mt * 16 + qrow + (r >> 1) * 8;
            const int m = m0 + row;
            const int b = m >> 12;
            const int s = m & (S_ - 1);
            const int cc = 2 * qcol + (r & 1);

            if (MODE == 0) {
#pragma unroll
                for (int nt = 0; nt < 4; nt++) {
                    int col = wn8 + nt * 32 + cc;
                    out[(size_t)m * D_ + n0 + col] = acc[mt][nt][r] + bias[n0 + col];
                }
            } else if (MODE == 3) {
#pragma unroll
                for (int nt = 0; nt < 4; nt++) {
                    int col = wn8 + nt * 32 + cc;
                    int h = (n0 + col) >> 6, e = col & 63;
                    g_Vh[(((size_t)b * H_ + h) * S_ + s) * HD_ + e] =
                        __float2half_rn(acc[mt][nt][r] + bias[n0 + col]);
                }
            } else {
                __half* dstb = (MODE == 1) ? g_Qh : g_Kh;
#pragma unroll
                for (int half = 0; half < 2; half++) {
                    const int p = half * 2;
                    const int h = (n0 >> 6) + half;
                    const int j = wn8 + cc;                      // 0..31
                    float x1 = acc[mt][p][r]     + bias[h * HD_ + j];
                    float x2 = acc[mt][p + 1][r] + bias[h * HD_ + j + 32];
                    float c1 = cs[s * HD_ + j],      s1 = sn[s * HD_ + j];
                    float c2 = cs[s * HD_ + j + 32], s2 = sn[s * HD_ + j + 32];
                    float r1 = x1 * c1 - x2 * s1;
                    float r2 = x2 * c2 + x1 * s2;
                    r1 = (r1 > 0.f) ? (r1 + 1.f) : expf(r1);
                    r2 = (r2 > 0.f) ? (r2 + 1.f) : expf(r2);
                    __half* d = dstb + (((size_t)b * H_ + h) * S_ + s) * HD_;
                    d[j]      = __float2half_rn(fmaxf(r1, 0.01f));
                    d[j + 32] = __float2half_rn(fmaxf(r2, 0.01f));
                }
            }
        }
    }
}

// ---------------------------------------------------------------------------
// kv_kernel: KVpart[bh][sp][d][e] = sum_{s in chunk} K[s][d] * V'[s][e]
// where V' = [V | 1 | 0...0] (ones column 64 -> KS computed by the same MMA).
// A = K^T via ldmatrix.trans, B = V' via ldmatrix.trans.
// Block: 128 thr (4 warps), warp = 16 d-rows x 72 e-cols, chunk = 256 s.
// ---------------------------------------------------------------------------
__global__ __launch_bounds__(128)
void kv_kernel()
{
    extern __shared__ __align__(16) char kvsm[];
    const int t = threadIdx.x, lane = t & 31, w = t >> 5;
    const int bh = blockIdx.y, sp = blockIdx.x;
    const uint32_t sK = smem_u32(kvsm);
    const uint32_t sV = sK + 256 * MPITCH;

    const __half* Kg = g_Kh + ((size_t)bh * S_ + sp * 256) * HD_;
    const __half* Vg = g_Vh + ((size_t)bh * S_ + sp * 256) * HD_;
#pragma unroll
    for (int j = 0; j < 16; j++) {
        int q = t + j * 128, row = q >> 3, seg = q & 7;
        CP16(sK + row * MPITCH + seg * 16, Kg + row * HD_ + seg * 8);
        CP16(sV + row * MPITCH + seg * 16, Vg + row * HD_ + seg * 8);
    }
    // fill V pad: col 64 = 1.0h, cols 65-71 = 0 (16B per row, rows t*2, t*2+1)
    {
        uint4 ones = make_uint4(0x00003C00u, 0u, 0u, 0u);
        *(uint4*)(kvsm + (256 * MPITCH) + (t * 2) * MPITCH + 128) = ones;
        *(uint4*)(kvsm + (256 * MPITCH) + (t * 2 + 1) * MPITCH + 128) = ones;
    }
    CP_COMMIT();
    CP_WAIT0();
    __syncthreads();

    const int g = lane >> 2, cc = lane & 3;
    const int d0 = w * 16;
    const uint32_t aBase = sK + ((lane & 7) + ((lane >> 4) << 3)) * MPITCH
                         + d0 * 2 + ((lane >> 3) & 1) * 16;
    const uint32_t bBase = sV + ((lane & 7) + ((lane >> 3) & 1) * 8) * MPITCH
                         + ((lane >> 4) << 4);
    const uint32_t b8Base = sV + ((lane & 7) + ((lane >> 3) & 1) * 8) * MPITCH + 128;

    float c[9][4];
#pragma unroll
    for (int nt = 0; nt < 9; nt++)
#pragma unroll
        for (int r = 0; r < 4; r++) c[nt][r] = 0.f;

#pragma unroll 4
    for (int s0 = 0; s0 < 256; s0 += 16) {
        uint32_t af[4];
        LDSM_X4_T(af[0], af[1], af[2], af[3], aBase + s0 * MPITCH);
#pragma unroll
        for (int nt2 = 0; nt2 < 4; nt2++) {
            uint32_t b0, b1, b2, b3;
            LDSM_X4_T(b0, b1, b2, b3, bBase + s0 * MPITCH + nt2 * 32);
            uint32_t bf0[2] = {b0, b1}, bf1[2] = {b2, b3};
            MMA_F16(c[2 * nt2],     af, bf0);
            MMA_F16(c[2 * nt2 + 1], af, bf1);
        }
        {   // KS tile (cols 64-71; col 64 = ones)
            uint32_t b0, b1;
            LDSM_X2_T(b0, b1, b8Base + s0 * MPITCH);
            uint32_t bf[2] = {b0, b1};
            MMA_F16(c[8], af, bf);
        }
    }

    float* dst = g_KVpart + (((size_t)bh * SPLIT_ + sp) * HD_ + d0 + g) * 72;
#pragma unroll
    for (int nt = 0; nt < 8; nt++) {
        *(float2*)(dst + 8 * nt + 2 * cc) = make_float2(c[nt][0], c[nt][1]);
        *(float2*)(dst + 8 * 72 + 8 * nt + 2 * cc) = make_float2(c[nt][2], c[nt][3]);
    }
    *(float2*)(dst + 64 + 2 * cc) = make_float2(c[8][0], c[8][1]);
    *(float2*)(dst + 8 * 72 + 64 + 2 * cc) = make_float2(c[8][2], c[8][3]);
}

// ---------------------------------------------------------------------------
// kv_reduce: g_KVh[bh][d][e] = fp16( sum_p KVpart[bh][p][d][e] ), e in [0,72)
// ---------------------------------------------------------------------------
__global__ void kv_reduce()
{
    int gi = blockIdx.x * blockDim.x + threadIdx.x;
    const int TOT = BH_ * HD_ * 72;
    if (gi >= TOT) return;
    int bh = gi / (HD_ * 72);
    int r  = gi % (HD_ * 72);
    float s = 0.f;
#pragma unroll
    for (int p = 0; p < SPLIT_; p++)
        s += g_KVpart[((size_t)bh * SPLIT_ + p) * (HD_ * 72) + r];
    g_KVh[gi] = __float2half_rn(s);
}

// ---------------------------------------------------------------------------
// apply: out[s][e] = (Q . KV)/clip(Q . KS) via one fp16 MMA sweep (N=72,
// norm = col 64). Writes g_O fp16 pair-permuted. Block = 64 s-rows, 4 warps.
// ---------------------------------------------------------------------------
__global__ __launch_bounds__(128)
void apply_kernel()
{
    __shared__ __align__(16) __half Qs[64 * 72];
    __shared__ __align__(16) __half KVs[64 * 72];
    const int t = threadIdx.x, lane = t & 31, w = t >> 5;
    const int bh = blockIdx.y;
    const int b = bh >> 4, h = bh & 15;
    const int s0blk = blockIdx.x * 64;
    const uint32_t sQ = smem_u32(Qs), sKV = smem_u32(KVs);

    const __half* Qg = g_Qh + ((size_t)bh * S_ + s0blk) * HD_;
#pragma unroll
    for (int j = 0; j < 4; j++) {
        int q = t + j * 128, row = q >> 3, seg = q & 7;
        CP16(sQ + row * MPITCH + seg * 16, Qg + row * HD_ + seg * 8);
    }
    const __half* KVg = g_KVh + (size_t)bh * HD_ * 72;
#pragma unroll
    for (int j = 0; j < 5; j++) {
        int q = t + j * 128;
        if (q < 576) CP16(sKV + q * 16, KVg + q * 8);
    }
    CP_COMMIT();
    CP_WAIT0();
    __syncthreads();

    const int g = lane >> 2, cc = lane & 3;
    const int m0 = w * 16;
    const uint32_t aBase = sQ + (m0 + (lane & 7) + ((lane >> 3) & 1) * 8) * MPITCH
                         + ((lane >> 4) << 4);
    const uint32_t bBase = sKV + ((lane & 7) + ((lane >> 3) & 1) * 8) * MPITCH
                         + ((lane >> 4) << 4);
    const uint32_t b8Base = sKV + ((lane & 7) + ((lane >> 3) & 1) * 8) * MPITCH + 128;

    float c[9][4];
#pragma unroll
    for (int nt = 0; nt < 9; nt++)
#pragma unroll
        for (int r = 0; r < 4; r++) c[nt][r] = 0.f;

#pragma unroll
    for (int k0 = 0; k0 < 64; k0 += 16) {
        uint32_t af[4];
        LDSM_X4(af[0], af[1], af[2], af[3], aBase + k0 * 2);
#pragma unroll
        for (int nt2 = 0; nt2 < 4; nt2++) {
            uint32_t b0, b1, b2, b3;
            LDSM_X4_T(b0, b1, b2, b3, bBase + k0 * MPITCH + nt2 * 32);
            uint32_t bf0[2] = {b0, b1}, bf1[2] = {b2, b3};
            MMA_F16(c[2 * nt2],     af, bf0);
            MMA_F16(c[2 * nt2 + 1], af, bf1);
        }
        {   // norm tile (cols 64-71)
            uint32_t b0, b1;
            LDSM_X2_T(b0, b1, b8Base + k0 * MPITCH);
            uint32_t bf[2] = {b0, b1};
            MMA_F16(c[8], af, bf);
        }
    }

    float n1 = __shfl_sync(0xFFFFFFFFu, c[8][0], lane & ~3);
    float n2 = __shfl_sync(0xFFFFFFFFu, c[8][2], lane & ~3);
    n1 = 1.0f / (fmaxf(n1, 1.0f) + 1e-6f);
    n2 = 1.0f / (fmaxf(n2, 1.0f) + 1e-6f);

    const int row1 = s0blk + m0 + g;
    const int row2 = row1 + 8;
#pragma unroll
    for (int nt = 0; nt < 8; nt++) {
        int e = 8 * nt + 2 * cc;
        int j = (4 * nt + cc) & 7;                   // pair index within 16-group
        int pp = (j < 4) ? 2 * j : 2 * (j - 4) + 1;  // permuted pair slot
        int col = h * HD_ + (e & ~15) + 2 * pp;
        *(__half2*)(g_O + ((size_t)b * S_ + row1) * D_ + col) =
            __floats2half2_rn(c[nt][0] * n1, c[nt][1] * n1);
        *(__half2*)(g_O + ((size_t)b * S_ + row2) * D_ + col) =
            __floats2half2_rn(c[nt][2] * n2, c[nt][3] * n2);
    }
}

// ---------------------------------------------------------------------------
extern "C" void kernel_launch(void* const* d_in, const int* in_sizes, int n_in,
                              void* d_out, int out_size)
{
    (void)in_sizes; (void)n_in; (void)out_size;
    const float* query = (const float*)d_in[0];
    const float* key   = (const float*)d_in[1];
    const float* value = (const float*)d_in[2];
    const float* cosp  = (const float*)d_in[3];
    const float* sinp  = (const float*)d_in[4];
    const float* Wq = (const float*)d_in[5];
    const float* bq = (const float*)d_in[6];
    const float* Wk = (const float*)d_in[7];
    const float* bk = (const float*)d_in[8];
    const float* Wv = (const float*)d_in[9];
    const float* bv = (const float*)d_in[10];
    const float* Wo = (const float*)d_in[11];
    const float* bo = (const float*)d_in[12];
    float* out = (float*)d_out;

    __half* pAh = nullptr; __half* pWh = nullptr;
    cudaGetSymbolAddress((void**)&pAh, g_Ah);
    cudaGetSymbolAddress((void**)&pWh, g_Wh);

    cudaFuncSetAttribute(gemm_tc<0>, cudaFuncAttributeMaxDynamicSharedMemorySize, SMEM_BYTES);
    cudaFuncSetAttribute(gemm_tc<1>, cudaFuncAttributeMaxDynamicSharedMemorySize, SMEM_BYTES);
    cudaFuncSetAttribute(gemm_tc<2>, cudaFuncAttributeMaxDynamicSharedMemorySize, SMEM_BYTES);
    cudaFuncSetAttribute(gemm_tc<3>, cudaFuncAttributeMaxDynamicSharedMemorySize, SMEM_BYTES);
    cudaFuncSetAttribute(kv_kernel, cudaFuncAttributeMaxDynamicSharedMemorySize, 2 * 256 * MPITCH);

    const size_t MD = (size_t)M_ * D_;
    const size_t DD = (size_t)D_ * D_;
    dim3 gt(D_ / TN, M_ / TM);        // (8, 128)

    conv_w_kernel<<<dim3((D_ * D_ / 16 + 255) / 256, 4), 256>>>(
        (const float4*)Wq, (const float4*)Wk, (const float4*)Wv, (const float4*)Wo);
    conv_act_kernel<<<dim3((M_ * D_ / 16 + 255) / 256, 3), 256>>>(
        (const float4*)query, (const float4*)key, (const float4*)value);

    gemm_tc<1><<<gt, 256, SMEM_BYTES>>>(pAh,          pWh,          bq, nullptr, cosp, sinp);
    gemm_tc<2><<<gt, 256, SMEM_BYTES>>>(pAh + MD,     pWh + DD,     bk, nullptr, cosp, sinp);
    gemm_tc<3><<<gt, 256, SMEM_BYTES>>>(pAh + 2 * MD, pWh + 2 * DD, bv, nullptr, cosp, sinp);

    kv_kernel<<<dim3(SPLIT_, BH_), 128, 2 * 256 * MPITCH>>>();
    kv_reduce<<<(BH_ * HD_ * 72 + 255) / 256, 256>>>();
    apply_kernel<<<dim3(S_ / 64, BH_), 128>>>();

    gemm_tc<0><<<gt, 256, SMEM_BYTES>>>(nullptr, pWh + 3 * DD, bo, out, nullptr, nullptr);
}

// round 12
// speedup vs baseline: 6.0707x; 1.1818x over previous
#include <cuda_runtime.h>
#include <cuda_fp16.h>
#include <cstdint>
#include <math.h>

#define B_ 4
#define S_ 4096
#define D_ 1024
#define H_ 16
#define HD_ 64
#define M_ (B_*S_)          // 16384
#define BH_ (B_*H_)         // 64
#define SPLIT_ 16

// GEMM tiling (fp16 mma.sync m16n8k16, fp32 accumulate)
#define TM 128
#define TN 128
#define BKH 64                      // halves per K-chunk = 128B row
#define NCH (D_/BKH)                // 16 chunks
#define PITCHB 160                  // bytes per smem row (bank-clean: 8*qrow+2*qcol)
#define STG_BYTES (128*PITCHB)      // 20480 per operand per stage
#define SMEM_BYTES (4*STG_BYTES)    // 2 stages x (A+B) = 81920 B -> 2 blocks/SM

// mid-section smem pitch: 144B per 72-half row -> conflict-free ldmatrix
#define MPITCH 144

// ---------------- scratch (device globals; no allocation) ----------------
__device__ __align__(16) __half g_Qh[(size_t)M_ * D_];  // [bh][s][d] fp16
__device__ __align__(16) __half g_Kh[(size_t)M_ * D_];
__device__ __align__(16) __half g_Vh[(size_t)M_ * D_];
__device__ __align__(16) __half g_O[(size_t)M_ * D_];   // [b,s,1024] fp16+perm
__device__ __align__(16) __half g_Ah[3][(size_t)M_ * D_]; // fp16+perm activations
__device__ __align__(16) __half g_Wh[4][(size_t)D_ * D_]; // fp16+perm weights
__device__ __align__(16) float  g_KVpart[(size_t)BH_ * SPLIT_ * HD_ * 72]; // [..][d][72]
__device__ __align__(16) __half g_KVh[(size_t)BH_ * HD_ * 72]; // [bh][d][72]: 0-63 KV, 64 KS

// ---------------- helpers ----------------
__device__ __forceinline__ uint32_t smem_u32(const void* p) {
    uint32_t a;
    asm("{ .reg .u64 t; cvta.to.shared.u64 t, %1; cvt.u32.u64 %0, t; }" : "=r"(a) : "l"(p));
    return a;
}
#define CP16(dst, src) asm volatile("cp.async.cg.shared.global [%0], [%1], 16;" :: "r"(dst), "l"(src))
#define CP_COMMIT()    asm volatile("cp.async.commit_group;" ::: "memory")
#define CP_WAIT1()     asm volatile("cp.async.wait_group 1;" ::: "memory")
#define CP_WAIT0()     asm volatile("cp.async.wait_group 0;" ::: "memory")

#define MMA_F16(c, a, b) \
    asm volatile("mma.sync.aligned.m16n8k16.row.col.f32.f16.f16.f32 " \
        "{%0,%1,%2,%3}, {%4,%5,%6,%7}, {%8,%9}, {%0,%1,%2,%3};" \
        : "+f"((c)[0]), "+f"((c)[1]), "+f"((c)[2]), "+f"((c)[3]) \
        : "r"((a)[0]), "r"((a)[1]), "r"((a)[2]), "r"((a)[3]), \
          "r"((b)[0]), "r"((b)[1]))

#define LDSM_X4(r0, r1, r2, r3, addr) \
    asm volatile("ldmatrix.sync.aligned.m8n8.x4.shared.b16 {%0,%1,%2,%3}, [%4];" \
        : "=r"(r0), "=r"(r1), "=r"(r2), "=r"(r3) : "r"(addr))
#define LDSM_X4_T(r0, r1, r2, r3, addr) \
    asm volatile("ldmatrix.sync.aligned.m8n8.x4.trans.shared.b16 {%0,%1,%2,%3}, [%4];" \
        : "=r"(r0), "=r"(r1), "=r"(r2), "=r"(r3) : "r"(addr))
#define LDSM_X2_T(r0, r1, addr) \
    asm volatile("ldmatrix.sync.aligned.m8n8.x2.trans.shared.b16 {%0,%1}, [%2];" \
        : "=r"(r0), "=r"(r1) : "r"(addr))

__device__ __forceinline__ uint32_t pack_h2(float lo, float hi) {
    __half2 h = __floats2half2_rn(lo, hi);
    return *reinterpret_cast<uint32_t*>(&h);
}

// ---------------------------------------------------------------------------
// fp32 -> fp16 RN + pair-permute within 16-groups: pairs out {0,4,1,5,2,6,3,7}
// ---------------------------------------------------------------------------
__device__ __forceinline__ void conv_body(const float4* __restrict__ src,
                                          uint4* __restrict__ dst, int i)
{
    float4 v0 = src[4 * i], v1 = src[4 * i + 1], v2 = src[4 * i + 2], v3 = src[4 * i + 3];
    uint4 o0, o1;
    o0.x = pack_h2(v0.x, v0.y);   o0.y = pack_h2(v2.x, v2.y);
    o0.z = pack_h2(v0.z, v0.w);   o0.w = pack_h2(v2.z, v2.w);
    o1.x = pack_h2(v1.x, v1.y);   o1.y = pack_h2(v3.x, v3.y);
    o1.z = pack_h2(v1.z, v1.w);   o1.w = pack_h2(v3.z, v3.w);
    dst[2 * i] = o0;  dst[2 * i + 1] = o1;
}

__global__ void conv_act_kernel(const float4* __restrict__ q, const float4* __restrict__ k,
                                const float4* __restrict__ v)
{
    int i = blockIdx.x * blockDim.x + threadIdx.x;
    const int n16 = M_ * D_ / 16;
    if (i < n16) {
        const float4* src = (blockIdx.y == 0) ? q : (blockIdx.y == 1) ? k : v;
        conv_body(src, (uint4*)(g_Ah[blockIdx.y]), i);
    }
}

__global__ void conv_w_kernel(const float4* __restrict__ w0, const float4* __restrict__ w1,
                              const float4* __restrict__ w2, const float4* __restrict__ w3)
{
    int i = blockIdx.x * blockDim.x + threadIdx.x;
    const int n16 = D_ * D_ / 16;
    if (i < n16) {
        const float4* src = (blockIdx.y == 0) ? w0 : (blockIdx.y == 1) ? w1
                          : (blockIdx.y == 2) ? w2 : w3;
        conv_body(src, (uint4*)(g_Wh[blockIdx.y]), i);
    }
}

// ---------------------------------------------------------------------------
// fp16 mma.sync GEMM  C = A @ W^T + bias. 2-stage cp.async, 2 blocks/SM.
// Tail fix: last iteration must drain ALL cp.async groups (wait_group 0) —
// wait_group 1 would let the final chunk's loads still be in flight.
// MODE: 0 plain->out(f32) ; 1 rope+elu->g_Qh ; 2 rope+elu->g_Kh ; 3 bias->g_Vh
// ---------------------------------------------------------------------------
template<int MODE>
__global__ __launch_bounds__(256, 2)
void gemm_tc(const __half* __restrict__ A, const __half* __restrict__ W,
             const float* __restrict__ bias, float* __restrict__ out,
             const float* __restrict__ cs, const float* __restrict__ sn)
{
    extern __shared__ __align__(16) char sm[];
    const int tid = threadIdx.x;
    const int n0  = blockIdx.x * TN;
    const int m0  = blockIdx.y * TM;
    const __half* __restrict__ Ap = (MODE == 0) ? (const __half*)g_O : A;

    const int lane = tid & 31;
    const int wid  = tid >> 5;
    const int wm64 = (wid & 1) * 64;
    const int wn8  = (wid >> 1) * 8;
    const int qrow = lane >> 2;
    const int qcol = lane & 3;
    const uint32_t sm_u = smem_u32(sm);

    auto load_chunk = [&](int ch, int st) {
        const int k0 = ch * BKH;
        const uint32_t aB = sm_u + (uint32_t)st * 2 * STG_BYTES;
        const uint32_t bB = aB + STG_BYTES;
#pragma unroll
        for (int j = 0; j < 4; j++) {
            int q = tid + j * 256, row = q >> 3, seg = q & 7;
            CP16(aB + (uint32_t)(row * PITCHB + seg * 16),
                 Ap + (size_t)(m0 + row) * D_ + k0 + seg * 8);
        }
#pragma unroll
        for (int j = 0; j < 4; j++) {
            int q = tid + j * 256, row = q >> 3, seg = q & 7;
            CP16(bB + (uint32_t)(row * PITCHB + seg * 16),
                 W + (size_t)(n0 + row) * D_ + k0 + seg * 8);
        }
    };

    float acc[4][4][4];
#pragma unroll
    for (int mt = 0; mt < 4; mt++)
#pragma unroll
        for (int nt = 0; nt < 4; nt++)
#pragma unroll
            for (int r = 0; r < 4; r++) acc[mt][nt][r] = 0.f;

    load_chunk(0, 0); CP_COMMIT();
    load_chunk(1, 1); CP_COMMIT();

    for (int i = 0; i < NCH; i++) {
        if (i == NCH - 1) CP_WAIT0();    // tail: drain EVERYTHING (fix)
        else              CP_WAIT1();    // chunk i resident (<=1 group pending)
        __syncthreads();

        const int st = i & 1;
        const char* As = sm + (size_t)st * 2 * STG_BYTES;
        const char* Bs = As + STG_BYTES;
#pragma unroll
        for (int kk = 0; kk < 4; kk++) {
            uint32_t bf[4][2];
#pragma unroll
            for (int nt = 0; nt < 4; nt++) {
                uint2 bv = *(const uint2*)(Bs + (wn8 + nt * 32 + qrow) * PITCHB + kk * 32 + 8 * qcol);
                bf[nt][0] = bv.x;  bf[nt][1] = bv.y;
            }
#pragma unroll
            for (int mt = 0; mt < 4; mt++) {
                const char* ap = As + (wm64 + mt * 16 + qrow) * PITCHB + kk * 32 + 8 * qcol;
                uint2 alo = *(const uint2*)ap;
                uint2 ahi = *(const uint2*)(ap + 8 * PITCHB);
                uint32_t af[4] = {alo.x, ahi.x, alo.y, ahi.y};
#pragma unroll
                for (int nt = 0; nt < 4; nt++) MMA_F16(acc[mt][nt], af, bf[nt]);
            }
        }

        if (i + 2 < NCH) {
            __syncthreads();             // all warps done reading stage st
            load_chunk(i + 2, st);
            CP_COMMIT();
        }
    }

    // ---------------- epilogue ----------------
#pragma unroll
    for (int mt = 0; mt < 4; mt++) {
#pragma unroll
        for (int r = 0; r < 4; r++) {
            const int row = wm64 + mt * 16 + qrow + (r >> 1) * 8;
            const int m = m0 + row;
            const int b = m >> 12;
            const int s = m & (S_ - 1);
            const int cc = 2 * qcol + (r & 1);

            if (MODE == 0) {
#pragma unroll
                for (int nt = 0; nt < 4; nt++) {
                    int col = wn8 + nt * 32 + cc;
                    out[(size_t)m * D_ + n0 + col] = acc[mt][nt][r] + bias[n0 + col];
                }
            } else if (MODE == 3) {
#pragma unroll
                for (int nt = 0; nt < 4; nt++) {
                    int col = wn8 + nt * 32 + cc;
                    int h = (n0 + col) >> 6, e = col & 63;
                    g_Vh[(((size_t)b * H_ + h) * S_ + s) * HD_ + e] =
                        __float2half_rn(acc[mt][nt][r] + bias[n0 + col]);
                }
            } else {
                __half* dstb = (MODE == 1) ? g_Qh : g_Kh;
#pragma unroll
                for (int half = 0; half < 2; half++) {
                    const int p = half * 2;
                    const int h = (n0 >> 6) + half;
                    const int j = wn8 + cc;                      // 0..31
                    float x1 = acc[mt][p][r]     + bias[h * HD_ + j];
                    float x2 = acc[mt][p + 1][r] + bias[h * HD_ + j + 32];
                    float c1 = cs[s * HD_ + j],      s1 = sn[s * HD_ + j];
                    float c2 = cs[s * HD_ + j + 32], s2 = sn[s * HD_ + j + 32];
                    float r1 = x1 * c1 - x2 * s1;
                    float r2 = x2 * c2 + x1 * s2;
                    r1 = (r1 > 0.f) ? (r1 + 1.f) : expf(r1);
                    r2 = (r2 > 0.f) ? (r2 + 1.f) : expf(r2);
                    __half* d = dstb + (((size_t)b * H_ + h) * S_ + s) * HD_;
                    d[j]      = __float2half_rn(fmaxf(r1, 0.01f));
                    d[j + 32] = __float2half_rn(fmaxf(r2, 0.01f));
                }
            }
        }
    }
}

// ---------------------------------------------------------------------------
// kv_kernel: KVpart[bh][sp][d][e] = sum_{s in chunk} K[s][d] * V'[s][e]
// where V' = [V | 1 | 0...0] (ones column 64 -> KS computed by the same MMA).
// ---------------------------------------------------------------------------
__global__ __launch_bounds__(128)
void kv_kernel()
{
    extern __shared__ __align__(16) char kvsm[];
    const int t = threadIdx.x, lane = t & 31, w = t >> 5;
    const int bh = blockIdx.y, sp = blockIdx.x;
    const uint32_t sK = smem_u32(kvsm);
    const uint32_t sV = sK + 256 * MPITCH;

    const __half* Kg = g_Kh + ((size_t)bh * S_ + sp * 256) * HD_;
    const __half* Vg = g_Vh + ((size_t)bh * S_ + sp * 256) * HD_;
#pragma unroll
    for (int j = 0; j < 16; j++) {
        int q = t + j * 128, row = q >> 3, seg = q & 7;
        CP16(sK + row * MPITCH + seg * 16, Kg + row * HD_ + seg * 8);
        CP16(sV + row * MPITCH + seg * 16, Vg + row * HD_ + seg * 8);
    }
    {   // V pad: col 64 = 1.0h, cols 65-71 = 0
        uint4 ones = make_uint4(0x00003C00u, 0u, 0u, 0u);
        *(uint4*)(kvsm + (256 * MPITCH) + (t * 2) * MPITCH + 128) = ones;
        *(uint4*)(kvsm + (256 * MPITCH) + (t * 2 + 1) * MPITCH + 128) = ones;
    }
    CP_COMMIT();
    CP_WAIT0();
    __syncthreads();

    const int g = lane >> 2, cc = lane & 3;
    const int d0 = w * 16;
    const uint32_t aBase = sK + ((lane & 7) + ((lane >> 4) << 3)) * MPITCH
                         + d0 * 2 + ((lane >> 3) & 1) * 16;
    const uint32_t bBase = sV + ((lane & 7) + ((lane >> 3) & 1) * 8) * MPITCH
                         + ((lane >> 4) << 4);
    const uint32_t b8Base = sV + ((lane & 7) + ((lane >> 3) & 1) * 8) * MPITCH + 128;

    float c[9][4];
#pragma unroll
    for (int nt = 0; nt < 9; nt++)
#pragma unroll
        for (int r = 0; r < 4; r++) c[nt][r] = 0.f;

#pragma unroll 4
    for (int s0 = 0; s0 < 256; s0 += 16) {
        uint32_t af[4];
        LDSM_X4_T(af[0], af[1], af[2], af[3], aBase + s0 * MPITCH);
#pragma unroll
        for (int nt2 = 0; nt2 < 4; nt2++) {
            uint32_t b0, b1, b2, b3;
            LDSM_X4_T(b0, b1, b2, b3, bBase + s0 * MPITCH + nt2 * 32);
            uint32_t bf0[2] = {b0, b1}, bf1[2] = {b2, b3};
            MMA_F16(c[2 * nt2],     af, bf0);
            MMA_F16(c[2 * nt2 + 1], af, bf1);
        }
        {   // KS tile (cols 64-71; col 64 = ones)
            uint32_t b0, b1;
            LDSM_X2_T(b0, b1, b8Base + s0 * MPITCH);
            uint32_t bf[2] = {b0, b1};
            MMA_F16(c[8], af, bf);
        }
    }

    float* dst = g_KVpart + (((size_t)bh * SPLIT_ + sp) * HD_ + d0 + g) * 72;
#pragma unroll
    for (int nt = 0; nt < 8; nt++) {
        *(float2*)(dst + 8 * nt + 2 * cc) = make_float2(c[nt][0], c[nt][1]);
        *(float2*)(dst + 8 * 72 + 8 * nt + 2 * cc) = make_float2(c[nt][2], c[nt][3]);
    }
    *(float2*)(dst + 64 + 2 * cc) = make_float2(c[8][0], c[8][1]);
    *(float2*)(dst + 8 * 72 + 64 + 2 * cc) = make_float2(c[8][2], c[8][3]);
}

// ---------------------------------------------------------------------------
// kv_reduce: g_KVh[bh][d][e] = fp16( sum_p KVpart[bh][p][d][e] ), e in [0,72)
// ---------------------------------------------------------------------------
__global__ void kv_reduce()
{
    int gi = blockIdx.x * blockDim.x + threadIdx.x;
    const int TOT = BH_ * HD_ * 72;
    if (gi >= TOT) return;
    int bh = gi / (HD_ * 72);
    int r  = gi % (HD_ * 72);
    float s = 0.f;
#pragma unroll
    for (int p = 0; p < SPLIT_; p++)
        s += g_KVpart[((size_t)bh * SPLIT_ + p) * (HD_ * 72) + r];
    g_KVh[gi] = __float2half_rn(s);
}

// ---------------------------------------------------------------------------
// apply: out[s][e] = (Q . KV)/clip(Q . KS) via one fp16 MMA sweep (N=72,
// norm = col 64). Writes g_O fp16 pair-permuted. Block = 64 s-rows, 4 warps.
// ---------------------------------------------------------------------------
__global__ __launch_bounds__(128)
void apply_kernel()
{
    __shared__ __align__(16) __half Qs[64 * 72];
    __shared__ __align__(16) __half KVs[64 * 72];
    const int t = threadIdx.x, lane = t & 31, w = t >> 5;
    const int bh = blockIdx.y;
    const int b = bh >> 4, h = bh & 15;
    const int s0blk = blockIdx.x * 64;
    const uint32_t sQ = smem_u32(Qs), sKV = smem_u32(KVs);

    const __half* Qg = g_Qh + ((size_t)bh * S_ + s0blk) * HD_;
#pragma unroll
    for (int j = 0; j < 4; j++) {
        int q = t + j * 128, row = q >> 3, seg = q & 7;
        CP16(sQ + row * MPITCH + seg * 16, Qg + row * HD_ + seg * 8);
    }
    const __half* KVg = g_KVh + (size_t)bh * HD_ * 72;
#pragma unroll
    for (int j = 0; j < 5; j++) {
        int q = t + j * 128;
        if (q < 576) CP16(sKV + q * 16, KVg + q * 8);
    }
    CP_COMMIT();
    CP_WAIT0();
    __syncthreads();

    const int g = lane >> 2, cc = lane & 3;
    const int m0 = w * 16;
    const uint32_t aBase = sQ + (m0 + (lane & 7) + ((lane >> 3) & 1) * 8) * MPITCH
                         + ((lane >> 4) << 4);
    const uint32_t bBase = sKV + ((lane & 7) + ((lane >> 3) & 1) * 8) * MPITCH
                         + ((lane >> 4) << 4);
    const uint32_t b8Base = sKV + ((lane & 7) + ((lane >> 3) & 1) * 8) * MPITCH + 128;

    float c[9][4];
#pragma unroll
    for (int nt = 0; nt < 9; nt++)
#pragma unroll
        for (int r = 0; r < 4; r++) c[nt][r] = 0.f;

#pragma unroll
    for (int k0 = 0; k0 < 64; k0 += 16) {
        uint32_t af[4];
        LDSM_X4(af[0], af[1], af[2], af[3], aBase + k0 * 2);
#pragma unroll
        for (int nt2 = 0; nt2 < 4; nt2++) {
            uint32_t b0, b1, b2, b3;
            LDSM_X4_T(b0, b1, b2, b3, bBase + k0 * MPITCH + nt2 * 32);
            uint32_t bf0[2] = {b0, b1}, bf1[2] = {b2, b3};
            MMA_F16(c[2 * nt2],     af, bf0);
            MMA_F16(c[2 * nt2 + 1], af, bf1);
        }
        {   // norm tile (cols 64-71)
            uint32_t b0, b1;
            LDSM_X2_T(b0, b1, b8Base + k0 * MPITCH);
            uint32_t bf[2] = {b0, b1};
            MMA_F16(c[8], af, bf);
        }
    }

    float n1 = __shfl_sync(0xFFFFFFFFu, c[8][0], lane & ~3);
    float n2 = __shfl_sync(0xFFFFFFFFu, c[8][2], lane & ~3);
    n1 = 1.0f / (fmaxf(n1, 1.0f) + 1e-6f);
    n2 = 1.0f / (fmaxf(n2, 1.0f) + 1e-6f);

    const int row1 = s0blk + m0 + g;
    const int row2 = row1 + 8;
#pragma unroll
    for (int nt = 0; nt < 8; nt++) {
        int e = 8 * nt + 2 * cc;
        int j = (4 * nt + cc) & 7;                   // pair index within 16-group
        int pp = (j < 4) ? 2 * j : 2 * (j - 4) + 1;  // permuted pair slot
        int col = h * HD_ + (e & ~15) + 2 * pp;
        *(__half2*)(g_O + ((size_t)b * S_ + row1) * D_ + col) =
            __floats2half2_rn(c[nt][0] * n1, c[nt][1] * n1);
        *(__half2*)(g_O + ((size_t)b * S_ + row2) * D_ + col) =
            __floats2half2_rn(c[nt][2] * n2, c[nt][3] * n2);
    }
}

// ---------------------------------------------------------------------------
extern "C" void kernel_launch(void* const* d_in, const int* in_sizes, int n_in,
                              void* d_out, int out_size)
{
    (void)in_sizes; (void)n_in; (void)out_size;
    const float* query = (const float*)d_in[0];
    const float* key   = (const float*)d_in[1];
    const float* value = (const float*)d_in[2];
    const float* cosp  = (const float*)d_in[3];
    const float* sinp  = (const float*)d_in[4];
    const float* Wq = (const float*)d_in[5];
    const float* bq = (const float*)d_in[6];
    const float* Wk = (const float*)d_in[7];
    const float* bk = (const float*)d_in[8];
    const float* Wv = (const float*)d_in[9];
    const float* bv = (const float*)d_in[10];
    const float* Wo = (const float*)d_in[11];
    const float* bo = (const float*)d_in[12];
    float* out = (float*)d_out;

    __half* pAh = nullptr; __half* pWh = nullptr;
    cudaGetSymbolAddress((void**)&pAh, g_Ah);
    cudaGetSymbolAddress((void**)&pWh, g_Wh);

    cudaFuncSetAttribute(gemm_tc<0>, cudaFuncAttributeMaxDynamicSharedMemorySize, SMEM_BYTES);
    cudaFuncSetAttribute(gemm_tc<1>, cudaFuncAttributeMaxDynamicSharedMemorySize, SMEM_BYTES);
    cudaFuncSetAttribute(gemm_tc<2>, cudaFuncAttributeMaxDynamicSharedMemorySize, SMEM_BYTES);
    cudaFuncSetAttribute(gemm_tc<3>, cudaFuncAttributeMaxDynamicSharedMemorySize, SMEM_BYTES);
    cudaFuncSetAttribute(kv_kernel, cudaFuncAttributeMaxDynamicSharedMemorySize, 2 * 256 * MPITCH);

    const size_t MD = (size_t)M_ * D_;
    const size_t DD = (size_t)D_ * D_;
    dim3 gt(D_ / TN, M_ / TM);        // (8, 128)

    conv_w_kernel<<<dim3((D_ * D_ / 16 + 255) / 256, 4), 256>>>(
        (const float4*)Wq, (const float4*)Wk, (const float4*)Wv, (const float4*)Wo);
    conv_act_kernel<<<dim3((M_ * D_ / 16 + 255) / 256, 3), 256>>>(
        (const float4*)query, (const float4*)key, (const float4*)value);

    gemm_tc<1><<<gt, 256, SMEM_BYTES>>>(pAh,          pWh,          bq, nullptr, cosp, sinp);
    gemm_tc<2><<<gt, 256, SMEM_BYTES>>>(pAh + MD,     pWh + DD,     bk, nullptr, cosp, sinp);
    gemm_tc<3><<<gt, 256, SMEM_BYTES>>>(pAh + 2 * MD, pWh + 2 * DD, bv, nullptr, cosp, sinp);

    kv_kernel<<<dim3(SPLIT_, BH_), 128, 2 * 256 * MPITCH>>>();
    kv_reduce<<<(BH_ * HD_ * 72 + 255) / 256, 256>>>();
    apply_kernel<<<dim3(S_ / 64, BH_), 128>>>();

    gemm_tc<0><<<gt, 256, SMEM_BYTES>>>(nullptr, pWh + 3 * DD, bo, out, nullptr, nullptr);
}